// round 12
// baseline (speedup 1.0000x reference)
#include <cuda_runtime.h>
#include <cuda_fp16.h>
#include <cstdint>

#define L_SIZE 65536
#define C_SIZE 32768
#define E_SIZE 262144
#define D 128
#define N_ITERS 4
#define NL_CTA (L_SIZE / 128)   // 512
#define NC_CTA (C_SIZE / 128)   // 256

// ================= device scratch =================
__device__ __align__(16) __half g_lemb[(size_t)L_SIZE * D];
__device__ __align__(16) __half g_cemb[(size_t)C_SIZE * D];
__device__ __align__(16) __half g_msg_l[(size_t)L_SIZE * D];
__device__ __align__(16) __half g_msg_c[(size_t)C_SIZE * D];
__device__ __align__(16) __half g_l2l[(size_t)L_SIZE * D];
__device__ __align__(16) __half g_wimg[22 * 8192];
__device__ int   g_cnt_l[L_SIZE], g_cnt_c[C_SIZE];
__device__ int   g_off_l[L_SIZE], g_off_c[C_SIZE];
__device__ int   g_cur_l[L_SIZE], g_cur_c[C_SIZE];
__device__ int   g_adj_c[E_SIZE];
__device__ int   g_adj_l[E_SIZE];
__device__ float g_inv_l[L_SIZE], g_inv_c[C_SIZE];
__device__ int   g_bsum[96];
__device__ int   g_idx64;

// ================= helpers =================
__device__ __forceinline__ uint32_t smem_u32(const void* p) {
    uint32_t a;
    asm("{ .reg .u64 t; cvta.to.shared.u64 t, %1; cvt.u32.u64 %0, t; }" : "=r"(a) : "l"(p));
    return a;
}
__device__ __forceinline__ int swz(int off) { return off ^ ((off >> 3) & 0x70); }

__device__ __forceinline__ void ldmx4(uint32_t* r, uint32_t addr) {
    asm volatile("ldmatrix.sync.aligned.m8n8.x4.shared.b16 {%0,%1,%2,%3}, [%4];"
                 : "=r"(r[0]), "=r"(r[1]), "=r"(r[2]), "=r"(r[3]) : "r"(addr));
}

__device__ __forceinline__ void mma16816(float (&c)[4], const uint32_t* a, const uint32_t* b) {
    asm volatile(
        "mma.sync.aligned.m16n8k16.row.col.f32.f16.f16.f32 "
        "{%0,%1,%2,%3}, {%4,%5,%6,%7}, {%8,%9}, {%0,%1,%2,%3};"
        : "+f"(c[0]), "+f"(c[1]), "+f"(c[2]), "+f"(c[3])
        : "r"(a[0]), "r"(a[1]), "r"(a[2]), "r"(a[3]), "r"(b[0]), "r"(b[1]));
}

__device__ __forceinline__ void cpa16(uint32_t dst, const void* src) {
    asm volatile("cp.async.cg.shared.global [%0], [%1], 16;" :: "r"(dst), "l"(src) : "memory");
}
#define CP_COMMIT() asm volatile("cp.async.commit_group;" ::: "memory")
#define CP_WAIT(n)  asm volatile("cp.async.wait_group %0;" :: "n"(n) : "memory")

// ===== SMEM maps (bytes) =====
// MLP: bias[512f]@0 (2048); A@2048 (2x16K); H@34816 (2x16K); W-ring @67584 (2x16K).
//      total 100352 -> occ 2.
#define M_A  2048
#define M_H  34816
#define M_W  67584
#define SMEM_MLP 100352
// UPD: bias@0 (1024); AG@1024 (2x16K); A-ring @33792 (2x16K); W-ring @66560 (2x16K).
//      total 99328 -> occ 2.
#define U_AG 1024
#define U_A  33792
#define U_W  66560
#define SMEM_UPD 99328

// ================= edge-index dtype handling =================
__device__ __forceinline__ int eidx(const void* p, int i, int f) {
    if (f) return (int)((const unsigned long long*)p)[i];
    return ((const int*)p)[i];
}

// L1: zero degree counters + dtype detect (block 0)
__global__ void k_zero_detect(const unsigned* p) {
    int i = blockIdx.x * 256 + threadIdx.x;        // grid 384 -> covers L+C
    if (i < L_SIZE) g_cnt_l[i] = 0;
    else g_cnt_c[i - L_SIZE] = 0;
    if (blockIdx.x == 0) {
        unsigned v = p[2 * threadIdx.x + 1];
        __shared__ int anynz;
        if (threadIdx.x == 0) anynz = 0;
        __syncthreads();
        unsigned b = __ballot_sync(0xffffffffu, v != 0u);
        if ((threadIdx.x & 31) == 0 && b) atomicExch(&anynz, 1);
        __syncthreads();
        if (threadIdx.x == 0) g_idx64 = (anynz == 0) ? 1 : 0;
    }
}
// L2
__global__ void k_hist(const void* lp, const void* cp) {
    int e = blockIdx.x * blockDim.x + threadIdx.x;
    int f = g_idx64;
    atomicAdd(&g_cnt_l[eidx(lp, e, f)], 1);
    atomicAdd(&g_cnt_c[eidx(cp, e, f)], 1);
}
// L3: merged block sums
__global__ void k_bsum_all() {
    __shared__ int sh[256];
    const int* cnt = (blockIdx.x < 64) ? g_cnt_l : g_cnt_c;
    int rel = (blockIdx.x < 64) ? blockIdx.x : blockIdx.x - 64;
    int base = rel * 1024 + threadIdx.x;
    int s = 0;
#pragma unroll
    for (int t = 0; t < 4; t++) s += cnt[base + t * 256];
    sh[threadIdx.x] = s;
    __syncthreads();
    for (int o = 128; o > 0; o >>= 1) {
        if (threadIdx.x < o) sh[threadIdx.x] += sh[threadIdx.x + o];
        __syncthreads();
    }
    if (threadIdx.x == 0) g_bsum[blockIdx.x] = sh[0];
}
// L4: blocks 0..95 scan+write offsets; blocks 96..117 weight-image prep (fp16)
__global__ void k_scanw_wprep(const float* w0, const float* w1, const float* w2,
                              const float* w3, const float* w4, const float* w5,
                              const float* wcu, const float* wlu) {
    int tid = threadIdx.x;
    if (blockIdx.x < 96) {
        __shared__ int sh[256];
        __shared__ int sb[64];
        int isl = blockIdx.x < 64;
        int lo = isl ? 0 : 64;
        int rel = blockIdx.x - lo;
        const int* cnt = isl ? g_cnt_l : g_cnt_c;
        int* off = isl ? g_off_l : g_off_c;
        int* cur = isl ? g_cur_l : g_cur_c;

        if (tid < 64) sb[tid] = (tid < rel) ? g_bsum[lo + tid] : 0;
        __syncthreads();
        for (int o = 32; o > 0; o >>= 1) {
            if (tid < o) sb[tid] += sb[tid + o];
            __syncthreads();
        }
        int base = sb[0];
        int base4 = rel * 1024 + tid * 4;
        int4 v = *(const int4*)(cnt + base4);
        int tsum = v.x + v.y + v.z + v.w;
        sh[tid] = tsum;
        __syncthreads();
        for (int o = 1; o < 256; o <<= 1) {
            int t = (tid >= o) ? sh[tid - o] : 0;
            __syncthreads();
            sh[tid] += t;
            __syncthreads();
        }
        int e = base + sh[tid] - tsum;
        off[base4 + 0] = e; cur[base4 + 0] = e; e += v.x;
        off[base4 + 1] = e; cur[base4 + 1] = e; e += v.y;
        off[base4 + 2] = e; cur[base4 + 2] = e; e += v.z;
        off[base4 + 3] = e; cur[base4 + 3] = e;
    } else {
        int half = blockIdx.x - 96;
        const float* W;
        int k0;
        if (half < 12) {
            const float* ws[6] = {w0, w1, w2, w3, w4, w5};
            W = ws[half >> 1];
            k0 = (half & 1) * 64;
        } else if (half < 16) {
            W = wcu; k0 = (half - 12) * 64;
        } else {
            W = wlu; k0 = (half - 16) * 64;
        }
        __half* oimg = g_wimg + (size_t)half * 8192;
        for (int idx = tid; idx < 8192; idx += 256) {
            int n = idx >> 6, k = idx & 63;
            float v = W[(size_t)(k0 + k) * 128 + n];
            int sw = swz(n * 128 + k * 2);
            *(unsigned short*)((char*)oimg + sw) =
                __half_as_ushort(__float2half_rn(v));
        }
    }
}
// L5: blocks 0..1023 CSR fill; 1024..1279 inv; 1280..7423 embedding init
__global__ void k_fill_inv_init(const void* lp, const void* cp,
                                const float* __restrict__ l_init,
                                const float* __restrict__ c_init) {
    int bid = blockIdx.x, tid = threadIdx.x;
    if (bid < 1024) {
        int e = bid * 256 + tid;
        int f = g_idx64;
        int li = eidx(lp, e, f);
        int ci = eidx(cp, e, f);
        g_adj_c[atomicAdd(&g_cur_c[ci], 1)] = li;
        g_adj_l[atomicAdd(&g_cur_l[li], 1)] = ci;
    } else if (bid < 1280) {
        int i = (bid - 1024) * 256 + tid;
        if (i < L_SIZE) { int c = g_cnt_l[i]; g_inv_l[i] = c ? rsqrtf((float)c) : 0.0f; }
        if (i < C_SIZE) { int c = g_cnt_c[i]; g_inv_c[i] = c ? rsqrtf((float)c) : 0.0f; }
    } else {
        int i = (bid - 1280) * 256 + tid;
        __half* emb;
        const float* init;
        int rel;
        if (i < L_SIZE * 16) { emb = g_lemb; init = l_init; rel = i; }
        else { emb = g_cemb; init = c_init; rel = i - L_SIZE * 16; }
        int c8 = (rel & 15) * 8;
        size_t base = (size_t)(rel >> 4) * 128 + c8;
        __half hv[8];
#pragma unroll
        for (int j = 0; j < 8; j++) hv[j] = __float2half_rn(init[c8 + j]);
        *(uint4*)(emb + base) = *(uint4*)hv;
    }
}

// ================= async tile fills =================
// full-K A tile (2 halves) from row-major fp16 gmem
__device__ __forceinline__ void issue_A_full(uint32_t a_base, const __half* __restrict__ X,
                                             size_t rowbase, int t) {
    for (int i = t; i < 2048; i += 256) {
        int row = i >> 4, u = i & 15;
        int half = u >> 3, uu = u & 7;
        cpa16(a_base + half * 16384 + swz(row * 128 + uu * 16),
              X + (rowbase + row) * 128 + u * 8);
    }
}
// one K=64 A half-tile
__device__ __forceinline__ void issue_A_half(uint32_t slot, const __half* __restrict__ X,
                                             size_t rowbase, int k64, int t) {
    for (int i = t; i < 1024; i += 256) {
        int row = i >> 3, uu = i & 7;
        cpa16(slot + swz(row * 128 + uu * 16),
              X + (rowbase + row) * 128 + k64 * 64 + uu * 8);
    }
}
// one 16K W slot from pre-swizzled image
__device__ __forceinline__ void issue_W(uint32_t slot, int wimg, int t) {
    const uint4* s = (const uint4*)(g_wimg + (size_t)wimg * 8192);
    for (int i = t; i < 1024; i += 256) cpa16(slot + i * 16, s + i);
}

// ================= warp GEMM over one K=64 half (single fp16 term) =================
__device__ __forceinline__ void warp_mma_k64(float (&acc)[16][4], uint32_t a_base,
                                             uint32_t w_base, int lane, int wid, int rxor) {
    const int wrow0 = (wid >> 1) * 32;
    const int nbase = (wid & 1) * 64;
#pragma unroll
    for (int kc = 0; kc < 4; kc++) {
        int kb = kc * 32;
        uint32_t ar[8];
#pragma unroll
        for (int mt = 0; mt < 2; mt++) {
            int arow = (wrow0 + mt * 16 + (lane & 15)) ^ rxor;
            int acol = kb + ((lane >> 4) << 4);
            ldmx4(ar + mt * 4, a_base + swz(arow * 128 + acol));
        }
        int brow = (lane & 7) + ((lane >> 4) & 1) * 8;
        int bcol = kb + (((lane >> 3) & 1) << 4);
        uint32_t br[16];
#pragma unroll
        for (int gg = 0; gg < 4; gg++)
            ldmx4(br + gg * 4, w_base + swz((nbase + gg * 16 + brow) * 128 + bcol));
#pragma unroll
        for (int mt = 0; mt < 2; mt++)
#pragma unroll
            for (int t = 0; t < 8; t++)
                mma16816(acc[mt * 8 + t], ar + mt * 4, br + (t >> 1) * 4 + (t & 1) * 2);
    }
}

// fragment -> relu/bias -> fp16 -> H region
__device__ __forceinline__ void store_H(char* hbase, float (&acc)[16][4],
                                        const float* __restrict__ b1s, int lane, int wid) {
    const int wrow0 = (wid >> 1) * 32;
    const int nbase = (wid & 1) * 64;
    int g = lane >> 2, tig = lane & 3;
#pragma unroll
    for (int mt = 0; mt < 2; mt++)
#pragma unroll
        for (int nt = 0; nt < 8; nt++) {
            int n = nbase + nt * 8 + 2 * tig;
            int half = n >> 6, kk = n & 63;
            float bz0 = b1s[n], bz1 = b1s[n + 1];
            const float* a = acc[mt * 8 + nt];
            int r0 = wrow0 + mt * 16 + g, r1 = r0 + 8;
            __half2 p0 = __floats2half2_rn(fmaxf(a[0] + bz0, 0.0f), fmaxf(a[1] + bz1, 0.0f));
            __half2 p1 = __floats2half2_rn(fmaxf(a[2] + bz0, 0.0f), fmaxf(a[3] + bz1, 0.0f));
            char* dh = hbase + half * 16384;
            *(uint32_t*)(dh + swz(r0 * 128 + kk * 2)) = *(uint32_t*)&p0;
            *(uint32_t*)(dh + swz(r1 * 128 + kk * 2)) = *(uint32_t*)&p1;
        }
}

// direct epilogue: fragments -> gmem (fp16 and/or fp32), optional per-row inv scale
__device__ __forceinline__ void epi_direct(float (&acc)[16][4], const float* __restrict__ bs,
                                           size_t rowbase, const float* __restrict__ inv,
                                           __half* __restrict__ outh,
                                           float* __restrict__ outf, int lane, int wid) {
    const int wrow0 = (wid >> 1) * 32;
    const int nbase = (wid & 1) * 64;
    int g = lane >> 2, tig = lane & 3;
#pragma unroll
    for (int mt = 0; mt < 2; mt++) {
        int r0 = wrow0 + mt * 16 + g, r1 = r0 + 8;
        float s0 = inv ? inv[rowbase + r0] : 1.0f;
        float s1 = inv ? inv[rowbase + r1] : 1.0f;
#pragma unroll
        for (int nt = 0; nt < 8; nt++) {
            int n = nbase + nt * 8 + 2 * tig;
            const float* a = acc[mt * 8 + nt];
            float v0 = (a[0] + bs[n]) * s0, v1 = (a[1] + bs[n + 1]) * s0;
            float v2 = (a[2] + bs[n]) * s1, v3 = (a[3] + bs[n + 1]) * s1;
            if (outh) {
                __half2 p0 = __floats2half2_rn(v0, v1);
                __half2 p1 = __floats2half2_rn(v2, v3);
                *(__half2*)(outh + (rowbase + r0) * 128 + n) = p0;
                *(__half2*)(outh + (rowbase + r1) * 128 + n) = p1;
            }
            if (outf) {
                *(float2*)(outf + (rowbase + r0) * 128 + n) = make_float2(v0, v1);
                *(float2*)(outf + (rowbase + r1) * 128 + n) = make_float2(v2, v3);
            }
        }
    }
}

#define ZERO_ACC(acc) do {                       \
    _Pragma("unroll")                            \
    for (int t_ = 0; t_ < 16; t_++)              \
        _Pragma("unroll")                        \
        for (int j_ = 0; j_ < 4; j_++) (acc)[t_][j_] = 0.0f; } while (0)

// ================= mega MLP kernel (occ 2, 2-slot W ring) =================
__global__ __launch_bounds__(256, 2) void k_mlp_all(
    const __half* __restrict__ lemb, const __half* __restrict__ cemb,
    const float* __restrict__ b_l2c1, const float* __restrict__ b_l2c2,
    const float* __restrict__ b_c2l1, const float* __restrict__ b_c2l2,
    const float* __restrict__ b_l2l1, const float* __restrict__ b_l2l2,
    const float* __restrict__ inv_l, const float* __restrict__ inv_c,
    __half* __restrict__ msg_l, __half* __restrict__ msg_c,
    __half* __restrict__ l2l) {
    extern __shared__ __align__(1024) char sm[];
    uint32_t smem_base = smem_u32(sm);
    float* bs = (float*)sm;
    int tid = threadIdx.x, wid = tid >> 5, lane = tid & 31;
    int bid = blockIdx.x;
    bool isL = bid < NL_CTA;
    size_t rowbase = isL ? (size_t)bid * 128 : (size_t)(bid - NL_CTA) * 128;
    const __half* X = isL ? lemb : cemb;
    int nstep = isL ? 8 : 4;

    if (isL) {
        for (int i = tid; i < 512; i += 256) {
            float v;
            if (i < 128) v = b_l2c1[i];
            else if (i < 256) v = b_l2c2[i - 128];
            else if (i < 384) v = b_l2l1[i - 256];
            else v = b_l2l2[i - 384];
            bs[i] = v;
        }
    } else {
        bs[tid] = (tid < 128) ? b_c2l1[tid] : b_c2l2[tid - 128];
    }

    uint32_t AB = smem_base + M_A, HB = smem_base + M_H, WB = smem_base + M_W;
    issue_A_full(AB, X, rowbase, tid);
    issue_W(WB, isL ? 0 : 4, tid);
    CP_COMMIT();

    float acc[16][4];
    ZERO_ACC(acc);

#pragma unroll 1
    for (int j = 0; j < nstep; j++) {
        __syncthreads();              // readers of slot (j+1)&1 (step j-1) done
        if (j + 1 < nstep) {
            int im = j + 1;
            int wimg = isL ? (im < 4 ? im : im + 4) : (4 + im);
            issue_W(WB + (im & 1) * 16384, wimg, tid);
            CP_COMMIT();
            CP_WAIT(1);               // group j complete
        } else {
            CP_WAIT(0);
        }
        __syncthreads();
        int ph = j >> 1;
        bool p2 = (ph & 1) != 0;
        uint32_t abase = (p2 ? HB : AB) + (j & 1) * 16384;
        int rxor = (isL && ph == 2) ? 1 : 0;
        warp_mma_k64(acc, abase, WB + (j & 1) * 16384, lane, wid, rxor);

        if (j & 1) {
            if (!p2) {
                store_H(sm + M_H, acc, bs + ((ph >> 1) * 256), lane, wid);
            } else {
                const float* b2 = bs + 128 + ((ph >> 1) * 256);
                if (!isL)
                    epi_direct(acc, b2, rowbase, inv_c, msg_c, nullptr, lane, wid);
                else if (ph == 1)
                    epi_direct(acc, b2, rowbase, inv_l, msg_l, nullptr, lane, wid);
                else
                    epi_direct(acc, b2, rowbase, nullptr, l2l, nullptr, lane, wid);
            }
            ZERO_ACC(acc);
        }
    }
}

// ================= mega update kernel (occ 2, fused aggregation) =================
// L chunks: 0,1 = emb; 2,3 = ag (in-smem gather); 4,5 = l2l.  C: 0,1 = emb; 2,3 = ag.
__global__ __launch_bounds__(256, 2) void k_upd_all(
    const __half* __restrict__ lemb, const __half* __restrict__ l2l,
    const __half* __restrict__ cemb,
    const __half* __restrict__ msg_l, const __half* __restrict__ msg_c,
    const float* __restrict__ b_lu, const float* __restrict__ b_cu,
    __half* __restrict__ olemb, __half* __restrict__ ocemb,
    float* __restrict__ fo) {
    extern __shared__ __align__(1024) char sm[];
    uint32_t smem_base = smem_u32(sm);
    float* bs = (float*)sm;
    int tid = threadIdx.x, wid = tid >> 5, lane = tid & 31;
    int bid = blockIdx.x;
    bool isL = bid < NL_CTA;
    size_t rowbase = isL ? (size_t)bid * 128 : (size_t)(bid - NL_CTA) * 128;
    int H = isL ? 6 : 4;
    int whalf = isL ? 16 : 12;
    const __half* emb = isL ? lemb : cemb;
    const __half* msg = isL ? msg_c : msg_l;
    const int* adj = isL ? g_adj_l : g_adj_c;
    const int* off = isL ? g_off_l : g_off_c;
    const int* cnt = isL ? g_cnt_l : g_cnt_c;
    const float* inv = isL ? g_inv_l : g_inv_c;

    if (tid < 128) bs[tid] = isL ? b_lu[tid] : b_cu[tid];

    uint32_t AGB = smem_base + U_AG, AB = smem_base + U_A, WB = smem_base + U_W;

    // prologue: chunk 0 (emb half0 + W0)
    issue_A_half(AB, emb, rowbase, 0, tid);
    issue_W(WB, whalf, tid);
    CP_COMMIT();

    // fused aggregation: ag tile for our 128 rows -> AG region (overlaps DMA above)
    {
        char* agc = sm + U_AG;
        int half = lane >> 4;                       // cols 4*lane: lane>=16 -> half 1
        int kk2 = ((4 * lane) & 63) * 2;            // byte offset of col pair base
#pragma unroll 1
        for (int r16 = 0; r16 < 16; r16++) {
            int r = wid * 16 + r16;
            int node = (int)rowbase + r;
            int o = off[node], d = cnt[node];
            float4 a1 = make_float4(0.f, 0.f, 0.f, 0.f);
            float4 a2 = make_float4(0.f, 0.f, 0.f, 0.f);
            int j = 0;
            for (; j + 2 <= d; j += 2) {
                int s0 = adj[o + j], s1 = adj[o + j + 1];
                uint2 v0 = *(const uint2*)(msg + (size_t)s0 * D + lane * 4);
                uint2 v1 = *(const uint2*)(msg + (size_t)s1 * D + lane * 4);
                float2 p00 = __half22float2(*(__half2*)&v0.x);
                float2 p01 = __half22float2(*(__half2*)&v0.y);
                float2 p10 = __half22float2(*(__half2*)&v1.x);
                float2 p11 = __half22float2(*(__half2*)&v1.y);
                a1.x += p00.x; a1.y += p00.y; a1.z += p01.x; a1.w += p01.y;
                a2.x += p10.x; a2.y += p10.y; a2.z += p11.x; a2.w += p11.y;
            }
            if (j < d) {
                int s0 = adj[o + j];
                uint2 v0 = *(const uint2*)(msg + (size_t)s0 * D + lane * 4);
                float2 p00 = __half22float2(*(__half2*)&v0.x);
                float2 p01 = __half22float2(*(__half2*)&v0.y);
                a1.x += p00.x; a1.y += p00.y; a1.z += p01.x; a1.w += p01.y;
            }
            float sc = inv[node];
            __half2 q0 = __floats2half2_rn((a1.x + a2.x) * sc, (a1.y + a2.y) * sc);
            __half2 q1 = __floats2half2_rn((a1.z + a2.z) * sc, (a1.w + a2.w) * sc);
            uint2 res;
            res.x = *(uint32_t*)&q0;
            res.y = *(uint32_t*)&q1;
            *(uint2*)(agc + half * 16384 + swz(r * 128 + kk2)) = res;
        }
    }

    float acc[16][4];
    ZERO_ACC(acc);

#pragma unroll 1
    for (int h = 0; h < H; h++) {
        __syncthreads();              // prev-step readers done; AG visible by h=2
        if (h + 1 < H) {
            int c = h + 1;
            if (c < 2) issue_A_half(AB + (c & 1) * 16384, emb, rowbase, c, tid);
            else if (c >= 4) issue_A_half(AB + (c & 1) * 16384, l2l, rowbase, c - 4, tid);
            issue_W(WB + (c & 1) * 16384, whalf + c, tid);
            CP_COMMIT();
            CP_WAIT(1);
        } else {
            CP_WAIT(0);
        }
        __syncthreads();
        uint32_t abase = (h == 2 || h == 3) ? (AGB + (h & 1) * 16384)
                                            : (AB + (h & 1) * 16384);
        warp_mma_k64(acc, abase, WB + (h & 1) * 16384, lane, wid, 0);
    }

    if (isL) epi_direct(acc, bs, rowbase, nullptr, olemb, fo, lane, wid);
    else epi_direct(acc, bs, rowbase, nullptr, ocemb, nullptr, lane, wid);
}

// ================= host launcher =================
extern "C" void kernel_launch(void* const* d_in, const int* in_sizes, int n_in,
                              void* d_out, int out_size) {
    const void* l_ei = d_in[0];
    const void* c_ei = d_in[1];
    const float* l_init = (const float*)d_in[2];
    const float* c_init = (const float*)d_in[3];
    const float* w_l2c1 = (const float*)d_in[4],  *b_l2c1 = (const float*)d_in[5];
    const float* w_l2c2 = (const float*)d_in[6],  *b_l2c2 = (const float*)d_in[7];
    const float* w_c2l1 = (const float*)d_in[8],  *b_c2l1 = (const float*)d_in[9];
    const float* w_c2l2 = (const float*)d_in[10], *b_c2l2 = (const float*)d_in[11];
    const float* w_l2l1 = (const float*)d_in[12], *b_l2l1 = (const float*)d_in[13];
    const float* w_l2l2 = (const float*)d_in[14], *b_l2l2 = (const float*)d_in[15];
    const float* w_cu   = (const float*)d_in[16], *b_cu   = (const float*)d_in[17];
    const float* w_lu   = (const float*)d_in[18], *b_lu   = (const float*)d_in[19];
    (void)in_sizes; (void)n_in; (void)out_size;

    __half *lemb, *cemb, *l2l, *msg_l, *msg_c;
    float *inv_l, *inv_c;
    cudaGetSymbolAddress((void**)&lemb, g_lemb);
    cudaGetSymbolAddress((void**)&cemb, g_cemb);
    cudaGetSymbolAddress((void**)&l2l, g_l2l);
    cudaGetSymbolAddress((void**)&msg_l, g_msg_l);
    cudaGetSymbolAddress((void**)&msg_c, g_msg_c);
    cudaGetSymbolAddress((void**)&inv_l, g_inv_l);
    cudaGetSymbolAddress((void**)&inv_c, g_inv_c);

    cudaFuncSetAttribute(k_mlp_all, cudaFuncAttributeMaxDynamicSharedMemorySize, SMEM_MLP);
    cudaFuncSetAttribute(k_upd_all, cudaFuncAttributeMaxDynamicSharedMemorySize, SMEM_UPD);

    // ---- setup: 5 launches (launch #6, the profiled one, is k_mlp_all) ----
    k_zero_detect<<<384, 256>>>((const unsigned*)l_ei);
    k_hist<<<E_SIZE / 256, 256>>>(l_ei, c_ei);
    k_bsum_all<<<96, 256>>>();
    k_scanw_wprep<<<118, 256>>>(w_l2c1, w_l2c2, w_c2l1, w_c2l2, w_l2l1, w_l2l2, w_cu, w_lu);
    k_fill_inv_init<<<7424, 256>>>(l_ei, c_ei, l_init, c_init);

    // ---- message-passing iterations: 2 launches each ----
    for (int it = 0; it < N_ITERS; it++) {
        k_mlp_all<<<NL_CTA + NC_CTA, 256, SMEM_MLP>>>(
            lemb, cemb,
            b_l2c1, b_l2c2, b_c2l1, b_c2l2, b_l2l1, b_l2l2,
            inv_l, inv_c, msg_l, msg_c, l2l);

        float* fo = (it == N_ITERS - 1) ? (float*)d_out : nullptr;
        k_upd_all<<<NL_CTA + NC_CTA, 256, SMEM_UPD>>>(
            lemb, l2l, cemb, msg_l, msg_c,
            b_lu, b_cu, lemb, cemb, fo);
    }
}

// round 13
// speedup vs baseline: 1.6073x; 1.6073x over previous
#include <cuda_runtime.h>
#include <cuda_fp16.h>
#include <cstdint>

#define L_SIZE 65536
#define C_SIZE 32768
#define E_SIZE 262144
#define D 128
#define N_ITERS 4
#define NL_CTA (L_SIZE / 128)   // 512
#define NC_CTA (C_SIZE / 128)   // 256

// ================= device scratch =================
__device__ __align__(16) __half g_lemb[(size_t)L_SIZE * D];
__device__ __align__(16) __half g_cemb[(size_t)C_SIZE * D];
__device__ __align__(16) __half g_msg_l[(size_t)L_SIZE * D];
__device__ __align__(16) __half g_msg_c[(size_t)C_SIZE * D];
__device__ __align__(16) __half g_l2l[(size_t)L_SIZE * D];
__device__ __align__(16) __half g_agl[(size_t)L_SIZE * D];
__device__ __align__(16) __half g_agc[(size_t)C_SIZE * D];
__device__ __align__(16) __half g_wimg[22 * 8192];
__device__ int   g_cnt_l[L_SIZE], g_cnt_c[C_SIZE];
__device__ int   g_off_l[L_SIZE], g_off_c[C_SIZE];
__device__ int   g_cur_l[L_SIZE], g_cur_c[C_SIZE];
__device__ int   g_adj_c[E_SIZE];
__device__ int   g_adj_l[E_SIZE];
__device__ float g_inv_l[L_SIZE], g_inv_c[C_SIZE];
__device__ int   g_bsum[96];
__device__ int   g_idx64;

// ================= helpers =================
__device__ __forceinline__ uint32_t smem_u32(const void* p) {
    uint32_t a;
    asm("{ .reg .u64 t; cvta.to.shared.u64 t, %1; cvt.u32.u64 %0, t; }" : "=r"(a) : "l"(p));
    return a;
}
__device__ __forceinline__ int swz(int off) { return off ^ ((off >> 3) & 0x70); }

__device__ __forceinline__ void ldmx4(uint32_t* r, uint32_t addr) {
    asm volatile("ldmatrix.sync.aligned.m8n8.x4.shared.b16 {%0,%1,%2,%3}, [%4];"
                 : "=r"(r[0]), "=r"(r[1]), "=r"(r[2]), "=r"(r[3]) : "r"(addr));
}

__device__ __forceinline__ void mma16816(float (&c)[4], const uint32_t* a, const uint32_t* b) {
    asm volatile(
        "mma.sync.aligned.m16n8k16.row.col.f32.f16.f16.f32 "
        "{%0,%1,%2,%3}, {%4,%5,%6,%7}, {%8,%9}, {%0,%1,%2,%3};"
        : "+f"(c[0]), "+f"(c[1]), "+f"(c[2]), "+f"(c[3])
        : "r"(a[0]), "r"(a[1]), "r"(a[2]), "r"(a[3]), "r"(b[0]), "r"(b[1]));
}

__device__ __forceinline__ void cpa16(uint32_t dst, const void* src) {
    asm volatile("cp.async.cg.shared.global [%0], [%1], 16;" :: "r"(dst), "l"(src) : "memory");
}
#define CP_COMMIT() asm volatile("cp.async.commit_group;" ::: "memory")
#define CP_WAIT(n)  asm volatile("cp.async.wait_group %0;" :: "n"(n) : "memory")

// ===== SMEM maps (bytes) =====
// MLP: bias[512f]@0 (2048); A@2048 (2x16K); H@34816 (2x16K); W-ring @67584 (2x16K).
//      total 100352 -> occ 2.
#define M_A  2048
#define M_H  34816
#define M_W  67584
#define SMEM_MLP 100352
// UPD: bias@0; 3 slots @2048, each 32K = [A 16K | W 16K]. total 100352 -> occ 2.
#define U_SL 2048
#define SMEM_UPD (2048 + 3 * 32768)

// ================= edge-index dtype handling =================
__device__ __forceinline__ int eidx(const void* p, int i, int f) {
    if (f) return (int)((const unsigned long long*)p)[i];
    return ((const int*)p)[i];
}

// L1: zero degree counters + dtype detect (block 0)
__global__ void k_zero_detect(const unsigned* p) {
    int i = blockIdx.x * 256 + threadIdx.x;        // grid 384 -> covers L+C
    if (i < L_SIZE) g_cnt_l[i] = 0;
    else g_cnt_c[i - L_SIZE] = 0;
    if (blockIdx.x == 0) {
        unsigned v = p[2 * threadIdx.x + 1];
        __shared__ int anynz;
        if (threadIdx.x == 0) anynz = 0;
        __syncthreads();
        unsigned b = __ballot_sync(0xffffffffu, v != 0u);
        if ((threadIdx.x & 31) == 0 && b) atomicExch(&anynz, 1);
        __syncthreads();
        if (threadIdx.x == 0) g_idx64 = (anynz == 0) ? 1 : 0;
    }
}
// L2
__global__ void k_hist(const void* lp, const void* cp) {
    int e = blockIdx.x * blockDim.x + threadIdx.x;
    int f = g_idx64;
    atomicAdd(&g_cnt_l[eidx(lp, e, f)], 1);
    atomicAdd(&g_cnt_c[eidx(cp, e, f)], 1);
}
// L3: merged block sums
__global__ void k_bsum_all() {
    __shared__ int sh[256];
    const int* cnt = (blockIdx.x < 64) ? g_cnt_l : g_cnt_c;
    int rel = (blockIdx.x < 64) ? blockIdx.x : blockIdx.x - 64;
    int base = rel * 1024 + threadIdx.x;
    int s = 0;
#pragma unroll
    for (int t = 0; t < 4; t++) s += cnt[base + t * 256];
    sh[threadIdx.x] = s;
    __syncthreads();
    for (int o = 128; o > 0; o >>= 1) {
        if (threadIdx.x < o) sh[threadIdx.x] += sh[threadIdx.x + o];
        __syncthreads();
    }
    if (threadIdx.x == 0) g_bsum[blockIdx.x] = sh[0];
}
// L4: blocks 0..95 scan+write offsets; blocks 96..117 weight-image prep (fp16)
__global__ void k_scanw_wprep(const float* w0, const float* w1, const float* w2,
                              const float* w3, const float* w4, const float* w5,
                              const float* wcu, const float* wlu) {
    int tid = threadIdx.x;
    if (blockIdx.x < 96) {
        __shared__ int sh[256];
        __shared__ int sb[64];
        int isl = blockIdx.x < 64;
        int lo = isl ? 0 : 64;
        int rel = blockIdx.x - lo;
        const int* cnt = isl ? g_cnt_l : g_cnt_c;
        int* off = isl ? g_off_l : g_off_c;
        int* cur = isl ? g_cur_l : g_cur_c;

        if (tid < 64) sb[tid] = (tid < rel) ? g_bsum[lo + tid] : 0;
        __syncthreads();
        for (int o = 32; o > 0; o >>= 1) {
            if (tid < o) sb[tid] += sb[tid + o];
            __syncthreads();
        }
        int base = sb[0];
        int base4 = rel * 1024 + tid * 4;
        int4 v = *(const int4*)(cnt + base4);
        int tsum = v.x + v.y + v.z + v.w;
        sh[tid] = tsum;
        __syncthreads();
        for (int o = 1; o < 256; o <<= 1) {
            int t = (tid >= o) ? sh[tid - o] : 0;
            __syncthreads();
            sh[tid] += t;
            __syncthreads();
        }
        int e = base + sh[tid] - tsum;
        off[base4 + 0] = e; cur[base4 + 0] = e; e += v.x;
        off[base4 + 1] = e; cur[base4 + 1] = e; e += v.y;
        off[base4 + 2] = e; cur[base4 + 2] = e; e += v.z;
        off[base4 + 3] = e; cur[base4 + 3] = e;
    } else {
        int half = blockIdx.x - 96;
        const float* W;
        int k0;
        if (half < 12) {
            const float* ws[6] = {w0, w1, w2, w3, w4, w5};
            W = ws[half >> 1];
            k0 = (half & 1) * 64;
        } else if (half < 16) {
            W = wcu; k0 = (half - 12) * 64;
        } else {
            W = wlu; k0 = (half - 16) * 64;
        }
        __half* oimg = g_wimg + (size_t)half * 8192;
        for (int idx = tid; idx < 8192; idx += 256) {
            int n = idx >> 6, k = idx & 63;
            float v = W[(size_t)(k0 + k) * 128 + n];
            int sw = swz(n * 128 + k * 2);
            *(unsigned short*)((char*)oimg + sw) =
                __half_as_ushort(__float2half_rn(v));
        }
    }
}
// L5: blocks 0..1023 CSR fill; 1024..1279 inv; 1280..7423 embedding init
__global__ void k_fill_inv_init(const void* lp, const void* cp,
                                const float* __restrict__ l_init,
                                const float* __restrict__ c_init) {
    int bid = blockIdx.x, tid = threadIdx.x;
    if (bid < 1024) {
        int e = bid * 256 + tid;
        int f = g_idx64;
        int li = eidx(lp, e, f);
        int ci = eidx(cp, e, f);
        g_adj_c[atomicAdd(&g_cur_c[ci], 1)] = li;
        g_adj_l[atomicAdd(&g_cur_l[li], 1)] = ci;
    } else if (bid < 1280) {
        int i = (bid - 1024) * 256 + tid;
        if (i < L_SIZE) { int c = g_cnt_l[i]; g_inv_l[i] = c ? rsqrtf((float)c) : 0.0f; }
        if (i < C_SIZE) { int c = g_cnt_c[i]; g_inv_c[i] = c ? rsqrtf((float)c) : 0.0f; }
    } else {
        int i = (bid - 1280) * 256 + tid;
        __half* emb;
        const float* init;
        int rel;
        if (i < L_SIZE * 16) { emb = g_lemb; init = l_init; rel = i; }
        else { emb = g_cemb; init = c_init; rel = i - L_SIZE * 16; }
        int c8 = (rel & 15) * 8;
        size_t base = (size_t)(rel >> 4) * 128 + c8;
        __half hv[8];
#pragma unroll
        for (int j = 0; j < 8; j++) hv[j] = __float2half_rn(init[c8 + j]);
        *(uint4*)(emb + base) = *(uint4*)hv;
    }
}

// ================= async tile fills =================
// full-K A tile (2 halves) from row-major fp16 gmem
__device__ __forceinline__ void issue_A_full(uint32_t a_base, const __half* __restrict__ X,
                                             size_t rowbase, int t) {
    for (int i = t; i < 2048; i += 256) {
        int row = i >> 4, u = i & 15;
        int half = u >> 3, uu = u & 7;
        cpa16(a_base + half * 16384 + swz(row * 128 + uu * 16),
              X + (rowbase + row) * 128 + u * 8);
    }
}
// one 16K W slot from pre-swizzled image
__device__ __forceinline__ void issue_W(uint32_t slot, int wimg, int t) {
    const uint4* s = (const uint4*)(g_wimg + (size_t)wimg * 8192);
    for (int i = t; i < 1024; i += 256) cpa16(slot + i * 16, s + i);
}
// one K=64 upd slot: [A 16K | W 16K]
__device__ __forceinline__ void issue_half(uint32_t slot, const __half* __restrict__ S,
                                           size_t rowbase, int k64, int wimg, int t) {
    const uint4* wsrc = (const uint4*)(g_wimg + (size_t)wimg * 8192);
    for (int i = t; i < 1024; i += 256) {
        int row = i >> 3, uu = i & 7;
        cpa16(slot + swz(row * 128 + uu * 16),
              S + (rowbase + row) * 128 + k64 * 64 + uu * 8);
        cpa16(slot + 16384 + i * 16, wsrc + i);
    }
}

// ================= warp GEMM over one K=64 half (single fp16 term) =================
// warp (wid>>1) owns rows [(wid>>1)*32,+32); (wid&1) owns cols [(wid&1)*64,+64)
__device__ __forceinline__ void warp_mma_k64(float (&acc)[16][4], uint32_t a_base,
                                             uint32_t w_base, int lane, int wid, int rxor) {
    const int wrow0 = (wid >> 1) * 32;
    const int nbase = (wid & 1) * 64;
#pragma unroll
    for (int kc = 0; kc < 4; kc++) {
        int kb = kc * 32;
        uint32_t ar[8];
#pragma unroll
        for (int mt = 0; mt < 2; mt++) {
            int arow = (wrow0 + mt * 16 + (lane & 15)) ^ rxor;
            int acol = kb + ((lane >> 4) << 4);
            ldmx4(ar + mt * 4, a_base + swz(arow * 128 + acol));
        }
        int brow = (lane & 7) + ((lane >> 4) & 1) * 8;
        int bcol = kb + (((lane >> 3) & 1) << 4);
        uint32_t br[16];
#pragma unroll
        for (int gg = 0; gg < 4; gg++)
            ldmx4(br + gg * 4, w_base + swz((nbase + gg * 16 + brow) * 128 + bcol));
#pragma unroll
        for (int mt = 0; mt < 2; mt++)
#pragma unroll
            for (int t = 0; t < 8; t++)
                mma16816(acc[mt * 8 + t], ar + mt * 4, br + (t >> 1) * 4 + (t & 1) * 2);
    }
}

// fragment -> relu/bias -> fp16 -> H region
__device__ __forceinline__ void store_H(char* hbase, float (&acc)[16][4],
                                        const float* __restrict__ b1s, int lane, int wid) {
    const int wrow0 = (wid >> 1) * 32;
    const int nbase = (wid & 1) * 64;
    int g = lane >> 2, tig = lane & 3;
#pragma unroll
    for (int mt = 0; mt < 2; mt++)
#pragma unroll
        for (int nt = 0; nt < 8; nt++) {
            int n = nbase + nt * 8 + 2 * tig;
            int half = n >> 6, kk = n & 63;
            float bz0 = b1s[n], bz1 = b1s[n + 1];
            const float* a = acc[mt * 8 + nt];
            int r0 = wrow0 + mt * 16 + g, r1 = r0 + 8;
            __half2 p0 = __floats2half2_rn(fmaxf(a[0] + bz0, 0.0f), fmaxf(a[1] + bz1, 0.0f));
            __half2 p1 = __floats2half2_rn(fmaxf(a[2] + bz0, 0.0f), fmaxf(a[3] + bz1, 0.0f));
            char* dh = hbase + half * 16384;
            *(uint32_t*)(dh + swz(r0 * 128 + kk * 2)) = *(uint32_t*)&p0;
            *(uint32_t*)(dh + swz(r1 * 128 + kk * 2)) = *(uint32_t*)&p1;
        }
}

// direct epilogue: fragments -> gmem (fp16 and/or fp32), optional per-row inv scale
__device__ __forceinline__ void epi_direct(float (&acc)[16][4], const float* __restrict__ bs,
                                           size_t rowbase, const float* __restrict__ inv,
                                           __half* __restrict__ outh,
                                           float* __restrict__ outf, int lane, int wid) {
    const int wrow0 = (wid >> 1) * 32;
    const int nbase = (wid & 1) * 64;
    int g = lane >> 2, tig = lane & 3;
#pragma unroll
    for (int mt = 0; mt < 2; mt++) {
        int r0 = wrow0 + mt * 16 + g, r1 = r0 + 8;
        float s0 = inv ? inv[rowbase + r0] : 1.0f;
        float s1 = inv ? inv[rowbase + r1] : 1.0f;
#pragma unroll
        for (int nt = 0; nt < 8; nt++) {
            int n = nbase + nt * 8 + 2 * tig;
            const float* a = acc[mt * 8 + nt];
            float v0 = (a[0] + bs[n]) * s0, v1 = (a[1] + bs[n + 1]) * s0;
            float v2 = (a[2] + bs[n]) * s1, v3 = (a[3] + bs[n + 1]) * s1;
            if (outh) {
                __half2 p0 = __floats2half2_rn(v0, v1);
                __half2 p1 = __floats2half2_rn(v2, v3);
                *(__half2*)(outh + (rowbase + r0) * 128 + n) = p0;
                *(__half2*)(outh + (rowbase + r1) * 128 + n) = p1;
            }
            if (outf) {
                *(float2*)(outf + (rowbase + r0) * 128 + n) = make_float2(v0, v1);
                *(float2*)(outf + (rowbase + r1) * 128 + n) = make_float2(v2, v3);
            }
        }
    }
}

#define ZERO_ACC(acc) do {                       \
    _Pragma("unroll")                            \
    for (int t_ = 0; t_ < 16; t_++)              \
        _Pragma("unroll")                        \
        for (int j_ = 0; j_ < 4; j_++) (acc)[t_][j_] = 0.0f; } while (0)

// ================= mega MLP kernel (occ 2, 2-slot W ring) =================
__global__ __launch_bounds__(256, 2) void k_mlp_all(
    const __half* __restrict__ lemb, const __half* __restrict__ cemb,
    const float* __restrict__ b_l2c1, const float* __restrict__ b_l2c2,
    const float* __restrict__ b_c2l1, const float* __restrict__ b_c2l2,
    const float* __restrict__ b_l2l1, const float* __restrict__ b_l2l2,
    const float* __restrict__ inv_l, const float* __restrict__ inv_c,
    __half* __restrict__ msg_l, __half* __restrict__ msg_c,
    __half* __restrict__ l2l) {
    extern __shared__ __align__(1024) char sm[];
    uint32_t smem_base = smem_u32(sm);
    float* bs = (float*)sm;
    int tid = threadIdx.x, wid = tid >> 5, lane = tid & 31;
    int bid = blockIdx.x;
    bool isL = bid < NL_CTA;
    size_t rowbase = isL ? (size_t)bid * 128 : (size_t)(bid - NL_CTA) * 128;
    const __half* X = isL ? lemb : cemb;
    int nstep = isL ? 8 : 4;

    if (isL) {
        for (int i = tid; i < 512; i += 256) {
            float v;
            if (i < 128) v = b_l2c1[i];
            else if (i < 256) v = b_l2c2[i - 128];
            else if (i < 384) v = b_l2l1[i - 256];
            else v = b_l2l2[i - 384];
            bs[i] = v;
        }
    } else {
        bs[tid] = (tid < 128) ? b_c2l1[tid] : b_c2l2[tid - 128];
    }

    uint32_t AB = smem_base + M_A, HB = smem_base + M_H, WB = smem_base + M_W;
    issue_A_full(AB, X, rowbase, tid);
    issue_W(WB, isL ? 0 : 4, tid);
    CP_COMMIT();

    float acc[16][4];
    ZERO_ACC(acc);

#pragma unroll 1
    for (int j = 0; j < nstep; j++) {
        __syncthreads();              // readers of slot (j+1)&1 (step j-1) done
        if (j + 1 < nstep) {
            int im = j + 1;
            int wimg = isL ? (im < 4 ? im : im + 4) : (4 + im);
            issue_W(WB + (im & 1) * 16384, wimg, tid);
            CP_COMMIT();
            CP_WAIT(1);               // group j complete
        } else {
            CP_WAIT(0);
        }
        __syncthreads();
        int ph = j >> 1;
        bool p2 = (ph & 1) != 0;
        uint32_t abase = (p2 ? HB : AB) + (j & 1) * 16384;
        int rxor = (isL && ph == 2) ? 1 : 0;
        warp_mma_k64(acc, abase, WB + (j & 1) * 16384, lane, wid, rxor);

        if (j & 1) {
            if (!p2) {
                store_H(sm + M_H, acc, bs + ((ph >> 1) * 256), lane, wid);
            } else {
                const float* b2 = bs + 128 + ((ph >> 1) * 256);
                if (!isL)
                    epi_direct(acc, b2, rowbase, inv_c, msg_c, nullptr, lane, wid);
                else if (ph == 1)
                    epi_direct(acc, b2, rowbase, inv_l, msg_l, nullptr, lane, wid);
                else
                    epi_direct(acc, b2, rowbase, nullptr, l2l, nullptr, lane, wid);
            }
            ZERO_ACC(acc);
        }
    }
}

// ================= mega update kernel (occ 2, 3-slot ring — R11 verbatim) =============
__global__ __launch_bounds__(256, 2) void k_upd_all(
    const __half* __restrict__ lemb, const __half* __restrict__ agl,
    const __half* __restrict__ l2l,
    const __half* __restrict__ cemb, const __half* __restrict__ agc,
    const float* __restrict__ b_lu, const float* __restrict__ b_cu,
    __half* __restrict__ olemb, __half* __restrict__ ocemb,
    float* __restrict__ fo) {
    extern __shared__ __align__(1024) char sm[];
    uint32_t smem_base = smem_u32(sm);
    float* bs = (float*)sm;
    int tid = threadIdx.x, wid = tid >> 5, lane = tid & 31;
    int bid = blockIdx.x;
    bool isL = bid < NL_CTA;
    size_t rowbase = isL ? (size_t)bid * 128 : (size_t)(bid - NL_CTA) * 128;
    int H = isL ? 6 : 4;
    int whalf = isL ? 16 : 12;

    if (tid < 128) bs[tid] = isL ? b_lu[tid] : b_cu[tid];

    const __half* S[3];
    if (isL) { S[0] = lemb; S[1] = agl; S[2] = l2l; }
    else { S[0] = cemb; S[1] = agc; S[2] = cemb; }

#pragma unroll
    for (int s = 0; s < 3; s++) {
        issue_half(smem_base + U_SL + s * 32768, S[s >> 1], rowbase, s & 1,
                   whalf + s, tid);
        CP_COMMIT();
    }

    float acc[16][4];
    ZERO_ACC(acc);

#pragma unroll 1
    for (int h = 0; h < H; h++) {
        if (h == 0) CP_WAIT(2);
        else if (h == H - 1) CP_WAIT(0);
        else CP_WAIT(1);
        __syncthreads();
        if (h >= 1 && h + 2 < H) {
            int s = h + 2;
            issue_half(smem_base + U_SL + (s % 3) * 32768, S[s >> 1], rowbase,
                       s & 1, whalf + s, tid);
            CP_COMMIT();
        }
        uint32_t slot = smem_base + U_SL + (h % 3) * 32768;
        warp_mma_k64(acc, slot, slot + 16384, lane, wid, 0);
    }

    if (isL) epi_direct(acc, bs, rowbase, nullptr, olemb, fo, lane, wid);
    else epi_direct(acc, bs, rowbase, nullptr, ocemb, nullptr, lane, wid);
}

// ================= merged CSR aggregation -> fp16 (R11 verbatim) =================
__global__ void k_aggr_all(const __half* __restrict__ msg_l, const __half* __restrict__ msg_c) {
    int w = blockIdx.x * 8 + (threadIdx.x >> 5);
    int lane = threadIdx.x & 31;
    const __half* msg;
    const int *adj, *off, *cnt;
    const float* inv;
    __half* out;
    int node;
    if (w < C_SIZE) {
        node = w; msg = msg_l; adj = g_adj_c; off = g_off_c; cnt = g_cnt_c;
        inv = g_inv_c; out = g_agc;
    } else {
        node = w - C_SIZE; msg = msg_c; adj = g_adj_l; off = g_off_l; cnt = g_cnt_l;
        inv = g_inv_l; out = g_agl;
    }
    int o = off[node], d = cnt[node];
    float4 acc = make_float4(0.f, 0.f, 0.f, 0.f);
    float4 acc2 = make_float4(0.f, 0.f, 0.f, 0.f);
    int j = 0;
    for (; j + 2 <= d; j += 2) {
        int s0 = adj[o + j], s1 = adj[o + j + 1];
        uint2 r0 = *(const uint2*)(msg + (size_t)s0 * D + lane * 4);
        uint2 r1 = *(const uint2*)(msg + (size_t)s1 * D + lane * 4);
        float2 a0 = __half22float2(*(__half2*)&r0.x);
        float2 a1 = __half22float2(*(__half2*)&r0.y);
        float2 b0 = __half22float2(*(__half2*)&r1.x);
        float2 b1 = __half22float2(*(__half2*)&r1.y);
        acc.x += a0.x; acc.y += a0.y; acc.z += a1.x; acc.w += a1.y;
        acc2.x += b0.x; acc2.y += b0.y; acc2.z += b1.x; acc2.w += b1.y;
    }
    if (j < d) {
        int s0 = adj[o + j];
        uint2 r0 = *(const uint2*)(msg + (size_t)s0 * D + lane * 4);
        float2 a0 = __half22float2(*(__half2*)&r0.x);
        float2 a1 = __half22float2(*(__half2*)&r0.y);
        acc.x += a0.x; acc.y += a0.y; acc.z += a1.x; acc.w += a1.y;
    }
    acc.x += acc2.x; acc.y += acc2.y; acc.z += acc2.z; acc.w += acc2.w;
    float sc = inv[node];
    __half2 p0 = __floats2half2_rn(acc.x * sc, acc.y * sc);
    __half2 p1 = __floats2half2_rn(acc.z * sc, acc.w * sc);
    uint2 res;
    res.x = *(uint32_t*)&p0;
    res.y = *(uint32_t*)&p1;
    *(uint2*)(out + (size_t)node * D + lane * 4) = res;
}

// ================= host launcher =================
extern "C" void kernel_launch(void* const* d_in, const int* in_sizes, int n_in,
                              void* d_out, int out_size) {
    const void* l_ei = d_in[0];
    const void* c_ei = d_in[1];
    const float* l_init = (const float*)d_in[2];
    const float* c_init = (const float*)d_in[3];
    const float* w_l2c1 = (const float*)d_in[4],  *b_l2c1 = (const float*)d_in[5];
    const float* w_l2c2 = (const float*)d_in[6],  *b_l2c2 = (const float*)d_in[7];
    const float* w_c2l1 = (const float*)d_in[8],  *b_c2l1 = (const float*)d_in[9];
    const float* w_c2l2 = (const float*)d_in[10], *b_c2l2 = (const float*)d_in[11];
    const float* w_l2l1 = (const float*)d_in[12], *b_l2l1 = (const float*)d_in[13];
    const float* w_l2l2 = (const float*)d_in[14], *b_l2l2 = (const float*)d_in[15];
    const float* w_cu   = (const float*)d_in[16], *b_cu   = (const float*)d_in[17];
    const float* w_lu   = (const float*)d_in[18], *b_lu   = (const float*)d_in[19];
    (void)in_sizes; (void)n_in; (void)out_size;

    __half *lemb, *cemb, *l2l, *agl, *agc, *msg_l, *msg_c;
    float *inv_l, *inv_c;
    cudaGetSymbolAddress((void**)&lemb, g_lemb);
    cudaGetSymbolAddress((void**)&cemb, g_cemb);
    cudaGetSymbolAddress((void**)&l2l, g_l2l);
    cudaGetSymbolAddress((void**)&agl, g_agl);
    cudaGetSymbolAddress((void**)&agc, g_agc);
    cudaGetSymbolAddress((void**)&msg_l, g_msg_l);
    cudaGetSymbolAddress((void**)&msg_c, g_msg_c);
    cudaGetSymbolAddress((void**)&inv_l, g_inv_l);
    cudaGetSymbolAddress((void**)&inv_c, g_inv_c);

    cudaFuncSetAttribute(k_mlp_all, cudaFuncAttributeMaxDynamicSharedMemorySize, SMEM_MLP);
    cudaFuncSetAttribute(k_upd_all, cudaFuncAttributeMaxDynamicSharedMemorySize, SMEM_UPD);

    // ---- setup: 5 launches ----
    k_zero_detect<<<384, 256>>>((const unsigned*)l_ei);
    k_hist<<<E_SIZE / 256, 256>>>(l_ei, c_ei);
    k_bsum_all<<<96, 256>>>();
    k_scanw_wprep<<<118, 256>>>(w_l2c1, w_l2c2, w_c2l1, w_c2l2, w_l2l1, w_l2l2, w_cu, w_lu);
    k_fill_inv_init<<<7424, 256>>>(l_ei, c_ei, l_init, c_init);

    // ---- message-passing iterations: 3 launches each ----
    for (int it = 0; it < N_ITERS; it++) {
        k_mlp_all<<<NL_CTA + NC_CTA, 256, SMEM_MLP>>>(
            lemb, cemb,
            b_l2c1, b_l2c2, b_c2l1, b_c2l2, b_l2l1, b_l2l2,
            inv_l, inv_c, msg_l, msg_c, l2l);

        k_aggr_all<<<(L_SIZE + C_SIZE) / 8, 256>>>(msg_l, msg_c);

        float* fo = (it == N_ITERS - 1) ? (float*)d_out : nullptr;
        k_upd_all<<<NL_CTA + NC_CTA, 256, SMEM_UPD>>>(
            lemb, agl, l2l, cemb, agc,
            b_lu, b_cu, lemb, cemb, fo);
    }
}

// round 14
// speedup vs baseline: 1.6518x; 1.0277x over previous
#include <cuda_runtime.h>
#include <cuda_fp16.h>
#include <cstdint>

#define L_SIZE 65536
#define C_SIZE 32768
#define E_SIZE 262144
#define D 128
#define N_ITERS 4
#define NL_CTA (L_SIZE / 128)   // 512
#define NC_CTA (C_SIZE / 128)   // 256

// ================= device scratch =================
__device__ __align__(16) __half g_lemb[(size_t)L_SIZE * D];
__device__ __align__(16) __half g_cemb[(size_t)C_SIZE * D];
__device__ __align__(16) __half g_msg_l[(size_t)L_SIZE * D];
__device__ __align__(16) __half g_msg_c[(size_t)C_SIZE * D];
__device__ __align__(16) __half g_l2l[(size_t)L_SIZE * D];
__device__ __align__(16) __half g_agl[(size_t)L_SIZE * D];
__device__ __align__(16) __half g_agc[(size_t)C_SIZE * D];
__device__ __align__(16) __half g_wimg[22 * 8192];
__device__ int   g_cnt_l[L_SIZE], g_cnt_c[C_SIZE];
__device__ int   g_off_l[L_SIZE], g_off_c[C_SIZE];
__device__ int   g_cur_l[L_SIZE], g_cur_c[C_SIZE];
__device__ int   g_adj_c[E_SIZE];
__device__ int   g_adj_l[E_SIZE];
__device__ float g_inv_l[L_SIZE], g_inv_c[C_SIZE];
__device__ int   g_bsum[96];
__device__ int   g_idx64;

// ================= helpers =================
__device__ __forceinline__ uint32_t smem_u32(const void* p) {
    uint32_t a;
    asm("{ .reg .u64 t; cvta.to.shared.u64 t, %1; cvt.u32.u64 %0, t; }" : "=r"(a) : "l"(p));
    return a;
}
__device__ __forceinline__ int swz(int off) { return off ^ ((off >> 3) & 0x70); }

__device__ __forceinline__ void ldmx4(uint32_t* r, uint32_t addr) {
    asm volatile("ldmatrix.sync.aligned.m8n8.x4.shared.b16 {%0,%1,%2,%3}, [%4];"
                 : "=r"(r[0]), "=r"(r[1]), "=r"(r[2]), "=r"(r[3]) : "r"(addr));
}

// fp16-accumulate HMMA: D/C fragment = 2 packed half2 regs
// reg0 = {d(r0,n), d(r0,n+1)}, reg1 = {d(r0+8,n), d(r0+8,n+1)}
__device__ __forceinline__ void mma16816h(uint32_t (&c)[2], const uint32_t* a,
                                          const uint32_t* b) {
    asm volatile(
        "mma.sync.aligned.m16n8k16.row.col.f16.f16.f16.f16 "
        "{%0,%1}, {%2,%3,%4,%5}, {%6,%7}, {%0,%1};"
        : "+r"(c[0]), "+r"(c[1])
        : "r"(a[0]), "r"(a[1]), "r"(a[2]), "r"(a[3]), "r"(b[0]), "r"(b[1]));
}

__device__ __forceinline__ void cpa16(uint32_t dst, const void* src) {
    asm volatile("cp.async.cg.shared.global [%0], [%1], 16;" :: "r"(dst), "l"(src) : "memory");
}
#define CP_COMMIT() asm volatile("cp.async.commit_group;" ::: "memory")
#define CP_WAIT(n)  asm volatile("cp.async.wait_group %0;" :: "n"(n) : "memory")

// ===== SMEM maps (bytes) =====
// MLP: bias[512f]@0 (2048); A@2048 (2x16K); H@34816 (2x16K); W-ring @67584 (3x16K).
//      total 116736 -> occ 1.   (R11 layout)
#define M_A  2048
#define M_H  34816
#define M_W  67584
#define SMEM_MLP 116736
// UPD: bias@0; 3 slots @2048, each 32K = [A 16K | W 16K]. total 100352 -> occ 2.
#define U_SL 2048
#define SMEM_UPD (2048 + 3 * 32768)

// ================= edge-index dtype handling =================
__device__ __forceinline__ int eidx(const void* p, int i, int f) {
    if (f) return (int)((const unsigned long long*)p)[i];
    return ((const int*)p)[i];
}

// L1: zero degree counters + dtype detect (block 0)
__global__ void k_zero_detect(const unsigned* p) {
    int i = blockIdx.x * 256 + threadIdx.x;        // grid 384 -> covers L+C
    if (i < L_SIZE) g_cnt_l[i] = 0;
    else g_cnt_c[i - L_SIZE] = 0;
    if (blockIdx.x == 0) {
        unsigned v = p[2 * threadIdx.x + 1];
        __shared__ int anynz;
        if (threadIdx.x == 0) anynz = 0;
        __syncthreads();
        unsigned b = __ballot_sync(0xffffffffu, v != 0u);
        if ((threadIdx.x & 31) == 0 && b) atomicExch(&anynz, 1);
        __syncthreads();
        if (threadIdx.x == 0) g_idx64 = (anynz == 0) ? 1 : 0;
    }
}
// L2
__global__ void k_hist(const void* lp, const void* cp) {
    int e = blockIdx.x * blockDim.x + threadIdx.x;
    int f = g_idx64;
    atomicAdd(&g_cnt_l[eidx(lp, e, f)], 1);
    atomicAdd(&g_cnt_c[eidx(cp, e, f)], 1);
}
// L3: merged block sums
__global__ void k_bsum_all() {
    __shared__ int sh[256];
    const int* cnt = (blockIdx.x < 64) ? g_cnt_l : g_cnt_c;
    int rel = (blockIdx.x < 64) ? blockIdx.x : blockIdx.x - 64;
    int base = rel * 1024 + threadIdx.x;
    int s = 0;
#pragma unroll
    for (int t = 0; t < 4; t++) s += cnt[base + t * 256];
    sh[threadIdx.x] = s;
    __syncthreads();
    for (int o = 128; o > 0; o >>= 1) {
        if (threadIdx.x < o) sh[threadIdx.x] += sh[threadIdx.x + o];
        __syncthreads();
    }
    if (threadIdx.x == 0) g_bsum[blockIdx.x] = sh[0];
}
// L4: blocks 0..95 scan+write offsets; blocks 96..117 weight-image prep (fp16)
__global__ void k_scanw_wprep(const float* w0, const float* w1, const float* w2,
                              const float* w3, const float* w4, const float* w5,
                              const float* wcu, const float* wlu) {
    int tid = threadIdx.x;
    if (blockIdx.x < 96) {
        __shared__ int sh[256];
        __shared__ int sb[64];
        int isl = blockIdx.x < 64;
        int lo = isl ? 0 : 64;
        int rel = blockIdx.x - lo;
        const int* cnt = isl ? g_cnt_l : g_cnt_c;
        int* off = isl ? g_off_l : g_off_c;
        int* cur = isl ? g_cur_l : g_cur_c;

        if (tid < 64) sb[tid] = (tid < rel) ? g_bsum[lo + tid] : 0;
        __syncthreads();
        for (int o = 32; o > 0; o >>= 1) {
            if (tid < o) sb[tid] += sb[tid + o];
            __syncthreads();
        }
        int base = sb[0];
        int base4 = rel * 1024 + tid * 4;
        int4 v = *(const int4*)(cnt + base4);
        int tsum = v.x + v.y + v.z + v.w;
        sh[tid] = tsum;
        __syncthreads();
        for (int o = 1; o < 256; o <<= 1) {
            int t = (tid >= o) ? sh[tid - o] : 0;
            __syncthreads();
            sh[tid] += t;
            __syncthreads();
        }
        int e = base + sh[tid] - tsum;
        off[base4 + 0] = e; cur[base4 + 0] = e; e += v.x;
        off[base4 + 1] = e; cur[base4 + 1] = e; e += v.y;
        off[base4 + 2] = e; cur[base4 + 2] = e; e += v.z;
        off[base4 + 3] = e; cur[base4 + 3] = e;
    } else {
        int half = blockIdx.x - 96;
        const float* W;
        int k0;
        if (half < 12) {
            const float* ws[6] = {w0, w1, w2, w3, w4, w5};
            W = ws[half >> 1];
            k0 = (half & 1) * 64;
        } else if (half < 16) {
            W = wcu; k0 = (half - 12) * 64;
        } else {
            W = wlu; k0 = (half - 16) * 64;
        }
        __half* oimg = g_wimg + (size_t)half * 8192;
        for (int idx = tid; idx < 8192; idx += 256) {
            int n = idx >> 6, k = idx & 63;
            float v = W[(size_t)(k0 + k) * 128 + n];
            int sw = swz(n * 128 + k * 2);
            *(unsigned short*)((char*)oimg + sw) =
                __half_as_ushort(__float2half_rn(v));
        }
    }
}
// L5: blocks 0..1023 CSR fill; 1024..1279 inv; 1280..7423 embedding init
__global__ void k_fill_inv_init(const void* lp, const void* cp,
                                const float* __restrict__ l_init,
                                const float* __restrict__ c_init) {
    int bid = blockIdx.x, tid = threadIdx.x;
    if (bid < 1024) {
        int e = bid * 256 + tid;
        int f = g_idx64;
        int li = eidx(lp, e, f);
        int ci = eidx(cp, e, f);
        g_adj_c[atomicAdd(&g_cur_c[ci], 1)] = li;
        g_adj_l[atomicAdd(&g_cur_l[li], 1)] = ci;
    } else if (bid < 1280) {
        int i = (bid - 1024) * 256 + tid;
        if (i < L_SIZE) { int c = g_cnt_l[i]; g_inv_l[i] = c ? rsqrtf((float)c) : 0.0f; }
        if (i < C_SIZE) { int c = g_cnt_c[i]; g_inv_c[i] = c ? rsqrtf((float)c) : 0.0f; }
    } else {
        int i = (bid - 1280) * 256 + tid;
        __half* emb;
        const float* init;
        int rel;
        if (i < L_SIZE * 16) { emb = g_lemb; init = l_init; rel = i; }
        else { emb = g_cemb; init = c_init; rel = i - L_SIZE * 16; }
        int c8 = (rel & 15) * 8;
        size_t base = (size_t)(rel >> 4) * 128 + c8;
        __half hv[8];
#pragma unroll
        for (int j = 0; j < 8; j++) hv[j] = __float2half_rn(init[c8 + j]);
        *(uint4*)(emb + base) = *(uint4*)hv;
    }
}

// ================= async tile fills =================
__device__ __forceinline__ void issue_A_full(uint32_t a_base, const __half* __restrict__ X,
                                             size_t rowbase, int t) {
    for (int i = t; i < 2048; i += 256) {
        int row = i >> 4, u = i & 15;
        int half = u >> 3, uu = u & 7;
        cpa16(a_base + half * 16384 + swz(row * 128 + uu * 16),
              X + (rowbase + row) * 128 + u * 8);
    }
}
__device__ __forceinline__ void issue_W(uint32_t slot, int wimg, int t) {
    const uint4* s = (const uint4*)(g_wimg + (size_t)wimg * 8192);
    for (int i = t; i < 1024; i += 256) cpa16(slot + i * 16, s + i);
}
__device__ __forceinline__ void issue_half(uint32_t slot, const __half* __restrict__ S,
                                           size_t rowbase, int k64, int wimg, int t) {
    const uint4* wsrc = (const uint4*)(g_wimg + (size_t)wimg * 8192);
    for (int i = t; i < 1024; i += 256) {
        int row = i >> 3, uu = i & 7;
        cpa16(slot + swz(row * 128 + uu * 16),
              S + (rowbase + row) * 128 + k64 * 64 + uu * 8);
        cpa16(slot + 16384 + i * 16, wsrc + i);
    }
}

// ================= warp GEMM over one K=64 half (fp16 accumulate) =================
// warp (wid>>1) owns rows [(wid>>1)*32,+32); (wid&1) owns cols [(wid&1)*64,+64)
__device__ __forceinline__ void warp_mma_k64(uint32_t (&acc)[16][2], uint32_t a_base,
                                             uint32_t w_base, int lane, int wid, int rxor) {
    const int wrow0 = (wid >> 1) * 32;
    const int nbase = (wid & 1) * 64;
#pragma unroll
    for (int kc = 0; kc < 4; kc++) {
        int kb = kc * 32;
        uint32_t ar[8];
#pragma unroll
        for (int mt = 0; mt < 2; mt++) {
            int arow = (wrow0 + mt * 16 + (lane & 15)) ^ rxor;
            int acol = kb + ((lane >> 4) << 4);
            ldmx4(ar + mt * 4, a_base + swz(arow * 128 + acol));
        }
        int brow = (lane & 7) + ((lane >> 4) & 1) * 8;
        int bcol = kb + (((lane >> 3) & 1) << 4);
        uint32_t br[16];
#pragma unroll
        for (int gg = 0; gg < 4; gg++)
            ldmx4(br + gg * 4, w_base + swz((nbase + gg * 16 + brow) * 128 + bcol));
#pragma unroll
        for (int mt = 0; mt < 2; mt++)
#pragma unroll
            for (int t = 0; t < 8; t++)
                mma16816h(acc[mt * 8 + t], ar + mt * 4, br + (t >> 1) * 4 + (t & 1) * 2);
    }
}

// fragment -> relu/bias -> fp16 -> H region
__device__ __forceinline__ void store_H(char* hbase, uint32_t (&acc)[16][2],
                                        const float* __restrict__ b1s, int lane, int wid) {
    const int wrow0 = (wid >> 1) * 32;
    const int nbase = (wid & 1) * 64;
    int g = lane >> 2, tig = lane & 3;
#pragma unroll
    for (int mt = 0; mt < 2; mt++)
#pragma unroll
        for (int nt = 0; nt < 8; nt++) {
            int n = nbase + nt * 8 + 2 * tig;
            int half = n >> 6, kk = n & 63;
            float bz0 = b1s[n], bz1 = b1s[n + 1];
            int r0 = wrow0 + mt * 16 + g, r1 = r0 + 8;
            float2 a0 = __half22float2(*(__half2*)&acc[mt * 8 + nt][0]);
            float2 a1 = __half22float2(*(__half2*)&acc[mt * 8 + nt][1]);
            __half2 p0 = __floats2half2_rn(fmaxf(a0.x + bz0, 0.0f), fmaxf(a0.y + bz1, 0.0f));
            __half2 p1 = __floats2half2_rn(fmaxf(a1.x + bz0, 0.0f), fmaxf(a1.y + bz1, 0.0f));
            char* dh = hbase + half * 16384;
            *(uint32_t*)(dh + swz(r0 * 128 + kk * 2)) = *(uint32_t*)&p0;
            *(uint32_t*)(dh + swz(r1 * 128 + kk * 2)) = *(uint32_t*)&p1;
        }
}

// direct epilogue: fragments -> gmem (fp16 and/or fp32), optional per-row inv scale
__device__ __forceinline__ void epi_direct(uint32_t (&acc)[16][2], const float* __restrict__ bs,
                                           size_t rowbase, const float* __restrict__ inv,
                                           __half* __restrict__ outh,
                                           float* __restrict__ outf, int lane, int wid) {
    const int wrow0 = (wid >> 1) * 32;
    const int nbase = (wid & 1) * 64;
    int g = lane >> 2, tig = lane & 3;
#pragma unroll
    for (int mt = 0; mt < 2; mt++) {
        int r0 = wrow0 + mt * 16 + g, r1 = r0 + 8;
        float s0 = inv ? inv[rowbase + r0] : 1.0f;
        float s1 = inv ? inv[rowbase + r1] : 1.0f;
#pragma unroll
        for (int nt = 0; nt < 8; nt++) {
            int n = nbase + nt * 8 + 2 * tig;
            float2 a0 = __half22float2(*(__half2*)&acc[mt * 8 + nt][0]);
            float2 a1 = __half22float2(*(__half2*)&acc[mt * 8 + nt][1]);
            float v0 = (a0.x + bs[n]) * s0, v1 = (a0.y + bs[n + 1]) * s0;
            float v2 = (a1.x + bs[n]) * s1, v3 = (a1.y + bs[n + 1]) * s1;
            if (outh) {
                __half2 p0 = __floats2half2_rn(v0, v1);
                __half2 p1 = __floats2half2_rn(v2, v3);
                *(__half2*)(outh + (rowbase + r0) * 128 + n) = p0;
                *(__half2*)(outh + (rowbase + r1) * 128 + n) = p1;
            }
            if (outf) {
                *(float2*)(outf + (rowbase + r0) * 128 + n) = make_float2(v0, v1);
                *(float2*)(outf + (rowbase + r1) * 128 + n) = make_float2(v2, v3);
            }
        }
    }
}

#define ZERO_ACC(acc) do {                       \
    _Pragma("unroll")                            \
    for (int t_ = 0; t_ < 16; t_++) {            \
        (acc)[t_][0] = 0u; (acc)[t_][1] = 0u; } } while (0)

// ================= mega MLP kernel (occ 1, 3-slot W ring — R11 structure) ============
__global__ __launch_bounds__(256, 1) void k_mlp_all(
    const __half* __restrict__ lemb, const __half* __restrict__ cemb,
    const float* __restrict__ b_l2c1, const float* __restrict__ b_l2c2,
    const float* __restrict__ b_c2l1, const float* __restrict__ b_c2l2,
    const float* __restrict__ b_l2l1, const float* __restrict__ b_l2l2,
    const float* __restrict__ inv_l, const float* __restrict__ inv_c,
    __half* __restrict__ msg_l, __half* __restrict__ msg_c,
    __half* __restrict__ l2l) {
    extern __shared__ __align__(1024) char sm[];
    uint32_t smem_base = smem_u32(sm);
    float* bs = (float*)sm;
    int tid = threadIdx.x, wid = tid >> 5, lane = tid & 31;
    int bid = blockIdx.x;
    bool isL = bid < NL_CTA;
    size_t rowbase = isL ? (size_t)bid * 128 : (size_t)(bid - NL_CTA) * 128;
    const __half* X = isL ? lemb : cemb;
    int nstep = isL ? 8 : 4;

    if (isL) {
        for (int i = tid; i < 512; i += 256) {
            float v;
            if (i < 128) v = b_l2c1[i];
            else if (i < 256) v = b_l2c2[i - 128];
            else if (i < 384) v = b_l2l1[i - 256];
            else v = b_l2l2[i - 384];
            bs[i] = v;
        }
    } else {
        bs[tid] = (tid < 128) ? b_c2l1[tid] : b_c2l2[tid - 128];
    }

    uint32_t AB = smem_base + M_A, HB = smem_base + M_H, WB = smem_base + M_W;
    issue_A_full(AB, X, rowbase, tid);
    issue_W(WB, isL ? 0 : 4, tid);
    CP_COMMIT();
    issue_W(WB + 16384, isL ? 1 : 5, tid);
    CP_COMMIT();
    issue_W(WB + 32768, isL ? 2 : 6, tid);
    CP_COMMIT();

    uint32_t acc[16][2];
    ZERO_ACC(acc);

#pragma unroll 1
    for (int j = 0; j < nstep; j++) {
        if (j == 0) CP_WAIT(2);
        else if (j == nstep - 1) CP_WAIT(0);
        else CP_WAIT(1);
        __syncthreads();
        if (j >= 1 && j + 2 < nstep) {
            int im = j + 2;
            int wimg = isL ? (im < 4 ? im : im + 4) : (4 + im);
            issue_W(WB + (im % 3) * 16384, wimg, tid);
            CP_COMMIT();
        }
        int ph = j >> 1;
        bool p2 = (ph & 1) != 0;
        uint32_t abase = (p2 ? HB : AB) + (j & 1) * 16384;
        int rxor = (isL && ph == 2) ? 1 : 0;
        warp_mma_k64(acc, abase, WB + (j % 3) * 16384, lane, wid, rxor);

        if (j & 1) {
            if (!p2) {
                store_H(sm + M_H, acc, bs + ((ph >> 1) * 256), lane, wid);
            } else {
                const float* b2 = bs + 128 + ((ph >> 1) * 256);
                if (!isL)
                    epi_direct(acc, b2, rowbase, inv_c, msg_c, nullptr, lane, wid);
                else if (ph == 1)
                    epi_direct(acc, b2, rowbase, inv_l, msg_l, nullptr, lane, wid);
                else
                    epi_direct(acc, b2, rowbase, nullptr, l2l, nullptr, lane, wid);
            }
            ZERO_ACC(acc);
        }
    }
}

// ================= mega update kernel (occ 2, 3-slot ring) =================
__global__ __launch_bounds__(256, 2) void k_upd_all(
    const __half* __restrict__ lemb, const __half* __restrict__ agl,
    const __half* __restrict__ l2l,
    const __half* __restrict__ cemb, const __half* __restrict__ agc,
    const float* __restrict__ b_lu, const float* __restrict__ b_cu,
    __half* __restrict__ olemb, __half* __restrict__ ocemb,
    float* __restrict__ fo) {
    extern __shared__ __align__(1024) char sm[];
    uint32_t smem_base = smem_u32(sm);
    float* bs = (float*)sm;
    int tid = threadIdx.x, wid = tid >> 5, lane = tid & 31;
    int bid = blockIdx.x;
    bool isL = bid < NL_CTA;
    size_t rowbase = isL ? (size_t)bid * 128 : (size_t)(bid - NL_CTA) * 128;
    int H = isL ? 6 : 4;
    int whalf = isL ? 16 : 12;

    if (tid < 128) bs[tid] = isL ? b_lu[tid] : b_cu[tid];

    const __half* S[3];
    if (isL) { S[0] = lemb; S[1] = agl; S[2] = l2l; }
    else { S[0] = cemb; S[1] = agc; S[2] = cemb; }

#pragma unroll
    for (int s = 0; s < 3; s++) {
        issue_half(smem_base + U_SL + s * 32768, S[s >> 1], rowbase, s & 1,
                   whalf + s, tid);
        CP_COMMIT();
    }

    uint32_t acc[16][2];
    ZERO_ACC(acc);

#pragma unroll 1
    for (int h = 0; h < H; h++) {
        if (h == 0) CP_WAIT(2);
        else if (h == H - 1) CP_WAIT(0);
        else CP_WAIT(1);
        __syncthreads();
        if (h >= 1 && h + 2 < H) {
            int s = h + 2;
            issue_half(smem_base + U_SL + (s % 3) * 32768, S[s >> 1], rowbase,
                       s & 1, whalf + s, tid);
            CP_COMMIT();
        }
        uint32_t slot = smem_base + U_SL + (h % 3) * 32768;
        warp_mma_k64(acc, slot, slot + 16384, lane, wid, 0);
    }

    if (isL) epi_direct(acc, bs, rowbase, nullptr, olemb, fo, lane, wid);
    else epi_direct(acc, bs, rowbase, nullptr, ocemb, nullptr, lane, wid);
}

// ================= merged CSR aggregation -> fp16 =================
__global__ void k_aggr_all(const __half* __restrict__ msg_l, const __half* __restrict__ msg_c) {
    int w = blockIdx.x * 8 + (threadIdx.x >> 5);
    int lane = threadIdx.x & 31;
    const __half* msg;
    const int *adj, *off, *cnt;
    const float* inv;
    __half* out;
    int node;
    if (w < C_SIZE) {
        node = w; msg = msg_l; adj = g_adj_c; off = g_off_c; cnt = g_cnt_c;
        inv = g_inv_c; out = g_agc;
    } else {
        node = w - C_SIZE; msg = msg_c; adj = g_adj_l; off = g_off_l; cnt = g_cnt_l;
        inv = g_inv_l; out = g_agl;
    }
    int o = off[node], d = cnt[node];
    float4 acc = make_float4(0.f, 0.f, 0.f, 0.f);
    float4 acc2 = make_float4(0.f, 0.f, 0.f, 0.f);
    int j = 0;
    for (; j + 2 <= d; j += 2) {
        int s0 = adj[o + j], s1 = adj[o + j + 1];
        uint2 r0 = *(const uint2*)(msg + (size_t)s0 * D + lane * 4);
        uint2 r1 = *(const uint2*)(msg + (size_t)s1 * D + lane * 4);
        float2 a0 = __half22float2(*(__half2*)&r0.x);
        float2 a1 = __half22float2(*(__half2*)&r0.y);
        float2 b0 = __half22float2(*(__half2*)&r1.x);
        float2 b1 = __half22float2(*(__half2*)&r1.y);
        acc.x += a0.x; acc.y += a0.y; acc.z += a1.x; acc.w += a1.y;
        acc2.x += b0.x; acc2.y += b0.y; acc2.z += b1.x; acc2.w += b1.y;
    }
    if (j < d) {
        int s0 = adj[o + j];
        uint2 r0 = *(const uint2*)(msg + (size_t)s0 * D + lane * 4);
        float2 a0 = __half22float2(*(__half2*)&r0.x);
        float2 a1 = __half22float2(*(__half2*)&r0.y);
        acc.x += a0.x; acc.y += a0.y; acc.z += a1.x; acc.w += a1.y;
    }
    acc.x += acc2.x; acc.y += acc2.y; acc.z += acc2.z; acc.w += acc2.w;
    float sc = inv[node];
    __half2 p0 = __floats2half2_rn(acc.x * sc, acc.y * sc);
    __half2 p1 = __floats2half2_rn(acc.z * sc, acc.w * sc);
    uint2 res;
    res.x = *(uint32_t*)&p0;
    res.y = *(uint32_t*)&p1;
    *(uint2*)(out + (size_t)node * D + lane * 4) = res;
}

// ================= host launcher =================
extern "C" void kernel_launch(void* const* d_in, const int* in_sizes, int n_in,
                              void* d_out, int out_size) {
    const void* l_ei = d_in[0];
    const void* c_ei = d_in[1];
    const float* l_init = (const float*)d_in[2];
    const float* c_init = (const float*)d_in[3];
    const float* w_l2c1 = (const float*)d_in[4],  *b_l2c1 = (const float*)d_in[5];
    const float* w_l2c2 = (const float*)d_in[6],  *b_l2c2 = (const float*)d_in[7];
    const float* w_c2l1 = (const float*)d_in[8],  *b_c2l1 = (const float*)d_in[9];
    const float* w_c2l2 = (const float*)d_in[10], *b_c2l2 = (const float*)d_in[11];
    const float* w_l2l1 = (const float*)d_in[12], *b_l2l1 = (const float*)d_in[13];
    const float* w_l2l2 = (const float*)d_in[14], *b_l2l2 = (const float*)d_in[15];
    const float* w_cu   = (const float*)d_in[16], *b_cu   = (const float*)d_in[17];
    const float* w_lu   = (const float*)d_in[18], *b_lu   = (const float*)d_in[19];
    (void)in_sizes; (void)n_in; (void)out_size;

    __half *lemb, *cemb, *l2l, *agl, *agc, *msg_l, *msg_c;
    float *inv_l, *inv_c;
    cudaGetSymbolAddress((void**)&lemb, g_lemb);
    cudaGetSymbolAddress((void**)&cemb, g_cemb);
    cudaGetSymbolAddress((void**)&l2l, g_l2l);
    cudaGetSymbolAddress((void**)&agl, g_agl);
    cudaGetSymbolAddress((void**)&agc, g_agc);
    cudaGetSymbolAddress((void**)&msg_l, g_msg_l);
    cudaGetSymbolAddress((void**)&msg_c, g_msg_c);
    cudaGetSymbolAddress((void**)&inv_l, g_inv_l);
    cudaGetSymbolAddress((void**)&inv_c, g_inv_c);

    cudaFuncSetAttribute(k_mlp_all, cudaFuncAttributeMaxDynamicSharedMemorySize, SMEM_MLP);
    cudaFuncSetAttribute(k_upd_all, cudaFuncAttributeMaxDynamicSharedMemorySize, SMEM_UPD);

    // ---- setup: 5 launches ----
    k_zero_detect<<<384, 256>>>((const unsigned*)l_ei);
    k_hist<<<E_SIZE / 256, 256>>>(l_ei, c_ei);
    k_bsum_all<<<96, 256>>>();
    k_scanw_wprep<<<118, 256>>>(w_l2c1, w_l2c2, w_c2l1, w_c2l2, w_l2l1, w_l2l2, w_cu, w_lu);
    k_fill_inv_init<<<7424, 256>>>(l_ei, c_ei, l_init, c_init);

    // ---- message-passing iterations: 3 launches each ----
    for (int it = 0; it < N_ITERS; it++) {
        k_mlp_all<<<NL_CTA + NC_CTA, 256, SMEM_MLP>>>(
            lemb, cemb,
            b_l2c1, b_l2c2, b_c2l1, b_c2l2, b_l2l1, b_l2l2,
            inv_l, inv_c, msg_l, msg_c, l2l);

        k_aggr_all<<<(L_SIZE + C_SIZE) / 8, 256>>>(msg_l, msg_c);

        float* fo = (it == N_ITERS - 1) ? (float*)d_out : nullptr;
        k_upd_all<<<NL_CTA + NC_CTA, 256, SMEM_UPD>>>(
            lemb, agl, l2l, cemb, agc,
            b_lu, b_cu, lemb, cemb, fo);
    }
}

// round 15
// speedup vs baseline: 1.8411x; 1.1146x over previous
#include <cuda_runtime.h>
#include <cuda_fp16.h>
#include <cstdint>

#define L_SIZE 65536
#define C_SIZE 32768
#define E_SIZE 262144
#define D 128
#define N_ITERS 4
#define NL_CTA (L_SIZE / 128)   // 512
#define NC_CTA (C_SIZE / 128)   // 256

// ================= device scratch =================
__device__ __align__(16) __half g_lemb[(size_t)L_SIZE * D];
__device__ __align__(16) __half g_cemb[(size_t)C_SIZE * D];
__device__ __align__(16) __half g_msg_l[(size_t)L_SIZE * D];
__device__ __align__(16) __half g_msg_c[(size_t)C_SIZE * D];
__device__ __align__(16) __half g_l2l[(size_t)L_SIZE * D];
__device__ __align__(16) __half g_agl[(size_t)L_SIZE * D];
__device__ __align__(16) __half g_agc[(size_t)C_SIZE * D];
__device__ __align__(16) __half g_wimg[22 * 8192];
__device__ int   g_cnt_l[L_SIZE], g_cnt_c[C_SIZE];
__device__ int   g_off_l[L_SIZE], g_off_c[C_SIZE];
__device__ int   g_cur_l[L_SIZE], g_cur_c[C_SIZE];
__device__ int   g_adj_c[E_SIZE];
__device__ int   g_adj_l[E_SIZE];
__device__ float g_inv_l[L_SIZE], g_inv_c[C_SIZE];
__device__ int   g_bsum[96];
__device__ int   g_idx64;

// ================= helpers =================
__device__ __forceinline__ uint32_t smem_u32(const void* p) {
    uint32_t a;
    asm("{ .reg .u64 t; cvta.to.shared.u64 t, %1; cvt.u32.u64 %0, t; }" : "=r"(a) : "l"(p));
    return a;
}
__device__ __forceinline__ int swz(int off) { return off ^ ((off >> 3) & 0x70); }

__device__ __forceinline__ void ldmx4(uint32_t* r, uint32_t addr) {
    asm volatile("ldmatrix.sync.aligned.m8n8.x4.shared.b16 {%0,%1,%2,%3}, [%4];"
                 : "=r"(r[0]), "=r"(r[1]), "=r"(r[2]), "=r"(r[3]) : "r"(addr));
}

__device__ __forceinline__ void mma16816(float (&c)[4], const uint32_t* a, const uint32_t* b) {
    asm volatile(
        "mma.sync.aligned.m16n8k16.row.col.f32.f16.f16.f32 "
        "{%0,%1,%2,%3}, {%4,%5,%6,%7}, {%8,%9}, {%0,%1,%2,%3};"
        : "+f"(c[0]), "+f"(c[1]), "+f"(c[2]), "+f"(c[3])
        : "r"(a[0]), "r"(a[1]), "r"(a[2]), "r"(a[3]), "r"(b[0]), "r"(b[1]));
}

__device__ __forceinline__ void cpa16(uint32_t dst, const void* src) {
    asm volatile("cp.async.cg.shared.global [%0], [%1], 16;" :: "r"(dst), "l"(src) : "memory");
}
#define CP_COMMIT() asm volatile("cp.async.commit_group;" ::: "memory")
#define CP_WAIT(n)  asm volatile("cp.async.wait_group %0;" :: "n"(n) : "memory")

// ===== SMEM maps (bytes) =====
// MLP: bias[512f]@0 (2048); A@2048 (2x16K); H@34816 (2x16K); W-ring @67584 (3x16K).
#define M_A  2048
#define M_H  34816
#define M_W  67584
#define SMEM_MLP 116736
// UPD: bias@0; 3 slots @2048, each 32K = [A 16K | W 16K]. -> occ 2.
#define U_SL 2048
#define SMEM_UPD (2048 + 3 * 32768)

// ================= edge-index dtype handling =================
__device__ __forceinline__ int eidx(const void* p, int i, int f) {
    if (f) return (int)((const unsigned long long*)p)[i];
    return ((const int*)p)[i];
}

__global__ void k_zero_detect(const unsigned* p) {
    int i = blockIdx.x * 256 + threadIdx.x;
    if (i < L_SIZE) g_cnt_l[i] = 0;
    else g_cnt_c[i - L_SIZE] = 0;
    if (blockIdx.x == 0) {
        unsigned v = p[2 * threadIdx.x + 1];
        __shared__ int anynz;
        if (threadIdx.x == 0) anynz = 0;
        __syncthreads();
        unsigned b = __ballot_sync(0xffffffffu, v != 0u);
        if ((threadIdx.x & 31) == 0 && b) atomicExch(&anynz, 1);
        __syncthreads();
        if (threadIdx.x == 0) g_idx64 = (anynz == 0) ? 1 : 0;
    }
}
__global__ void k_hist(const void* lp, const void* cp) {
    int e = blockIdx.x * blockDim.x + threadIdx.x;
    int f = g_idx64;
    atomicAdd(&g_cnt_l[eidx(lp, e, f)], 1);
    atomicAdd(&g_cnt_c[eidx(cp, e, f)], 1);
}
__global__ void k_bsum_all() {
    __shared__ int sh[256];
    const int* cnt = (blockIdx.x < 64) ? g_cnt_l : g_cnt_c;
    int rel = (blockIdx.x < 64) ? blockIdx.x : blockIdx.x - 64;
    int base = rel * 1024 + threadIdx.x;
    int s = 0;
#pragma unroll
    for (int t = 0; t < 4; t++) s += cnt[base + t * 256];
    sh[threadIdx.x] = s;
    __syncthreads();
    for (int o = 128; o > 0; o >>= 1) {
        if (threadIdx.x < o) sh[threadIdx.x] += sh[threadIdx.x + o];
        __syncthreads();
    }
    if (threadIdx.x == 0) g_bsum[blockIdx.x] = sh[0];
}
__global__ void k_scanw_wprep(const float* w0, const float* w1, const float* w2,
                              const float* w3, const float* w4, const float* w5,
                              const float* wcu, const float* wlu) {
    int tid = threadIdx.x;
    if (blockIdx.x < 96) {
        __shared__ int sh[256];
        __shared__ int sb[64];
        int isl = blockIdx.x < 64;
        int lo = isl ? 0 : 64;
        int rel = blockIdx.x - lo;
        const int* cnt = isl ? g_cnt_l : g_cnt_c;
        int* off = isl ? g_off_l : g_off_c;
        int* cur = isl ? g_cur_l : g_cur_c;

        if (tid < 64) sb[tid] = (tid < rel) ? g_bsum[lo + tid] : 0;
        __syncthreads();
        for (int o = 32; o > 0; o >>= 1) {
            if (tid < o) sb[tid] += sb[tid + o];
            __syncthreads();
        }
        int base = sb[0];
        int base4 = rel * 1024 + tid * 4;
        int4 v = *(const int4*)(cnt + base4);
        int tsum = v.x + v.y + v.z + v.w;
        sh[tid] = tsum;
        __syncthreads();
        for (int o = 1; o < 256; o <<= 1) {
            int t = (tid >= o) ? sh[tid - o] : 0;
            __syncthreads();
            sh[tid] += t;
            __syncthreads();
        }
        int e = base + sh[tid] - tsum;
        off[base4 + 0] = e; cur[base4 + 0] = e; e += v.x;
        off[base4 + 1] = e; cur[base4 + 1] = e; e += v.y;
        off[base4 + 2] = e; cur[base4 + 2] = e; e += v.z;
        off[base4 + 3] = e; cur[base4 + 3] = e;
    } else {
        int half = blockIdx.x - 96;
        const float* W;
        int k0;
        if (half < 12) {
            const float* ws[6] = {w0, w1, w2, w3, w4, w5};
            W = ws[half >> 1];
            k0 = (half & 1) * 64;
        } else if (half < 16) {
            W = wcu; k0 = (half - 12) * 64;
        } else {
            W = wlu; k0 = (half - 16) * 64;
        }
        __half* oimg = g_wimg + (size_t)half * 8192;
        for (int idx = tid; idx < 8192; idx += 256) {
            int n = idx >> 6, k = idx & 63;
            float v = W[(size_t)(k0 + k) * 128 + n];
            int sw = swz(n * 128 + k * 2);
            *(unsigned short*)((char*)oimg + sw) =
                __half_as_ushort(__float2half_rn(v));
        }
    }
}
__global__ void k_fill_inv_init(const void* lp, const void* cp,
                                const float* __restrict__ l_init,
                                const float* __restrict__ c_init) {
    int bid = blockIdx.x, tid = threadIdx.x;
    if (bid < 1024) {
        int e = bid * 256 + tid;
        int f = g_idx64;
        int li = eidx(lp, e, f);
        int ci = eidx(cp, e, f);
        g_adj_c[atomicAdd(&g_cur_c[ci], 1)] = li;
        g_adj_l[atomicAdd(&g_cur_l[li], 1)] = ci;
    } else if (bid < 1280) {
        int i = (bid - 1024) * 256 + tid;
        if (i < L_SIZE) { int c = g_cnt_l[i]; g_inv_l[i] = c ? rsqrtf((float)c) : 0.0f; }
        if (i < C_SIZE) { int c = g_cnt_c[i]; g_inv_c[i] = c ? rsqrtf((float)c) : 0.0f; }
    } else {
        int i = (bid - 1280) * 256 + tid;
        __half* emb;
        const float* init;
        int rel;
        if (i < L_SIZE * 16) { emb = g_lemb; init = l_init; rel = i; }
        else { emb = g_cemb; init = c_init; rel = i - L_SIZE * 16; }
        int c8 = (rel & 15) * 8;
        size_t base = (size_t)(rel >> 4) * 128 + c8;
        __half hv[8];
#pragma unroll
        for (int j = 0; j < 8; j++) hv[j] = __float2half_rn(init[c8 + j]);
        *(uint4*)(emb + base) = *(uint4*)hv;
    }
}

// ================= async tile fills =================
__device__ __forceinline__ void issue_A_full(uint32_t a_base, const __half* __restrict__ X,
                                             size_t rowbase, int t) {
    for (int i = t; i < 2048; i += 256) {
        int row = i >> 4, u = i & 15;
        int half = u >> 3, uu = u & 7;
        cpa16(a_base + half * 16384 + swz(row * 128 + uu * 16),
              X + (rowbase + row) * 128 + u * 8);
    }
}
__device__ __forceinline__ void issue_W(uint32_t slot, int wimg, int t) {
    const uint4* s = (const uint4*)(g_wimg + (size_t)wimg * 8192);
    for (int i = t; i < 1024; i += 256) cpa16(slot + i * 16, s + i);
}
__device__ __forceinline__ void issue_half(uint32_t slot, const __half* __restrict__ S,
                                           size_t rowbase, int k64, int wimg, int t) {
    const uint4* wsrc = (const uint4*)(g_wimg + (size_t)wimg * 8192);
    for (int i = t; i < 1024; i += 256) {
        int row = i >> 3, uu = i & 7;
        cpa16(slot + swz(row * 128 + uu * 16),
              S + (rowbase + row) * 128 + k64 * 64 + uu * 8);
        cpa16(slot + 16384 + i * 16, wsrc + i);
    }
}

// ================= warp GEMM over one K=64 half =================
__device__ __forceinline__ void warp_mma_k64(float (&acc)[16][4], uint32_t a_base,
                                             uint32_t w_base, int lane, int wid, int rxor) {
    const int wrow0 = (wid >> 1) * 32;
    const int nbase = (wid & 1) * 64;
#pragma unroll
    for (int kc = 0; kc < 4; kc++) {
        int kb = kc * 32;
        uint32_t ar[8];
#pragma unroll
        for (int mt = 0; mt < 2; mt++) {
            int arow = (wrow0 + mt * 16 + (lane & 15)) ^ rxor;
            int acol = kb + ((lane >> 4) << 4);
            ldmx4(ar + mt * 4, a_base + swz(arow * 128 + acol));
        }
        int brow = (lane & 7) + ((lane >> 4) & 1) * 8;
        int bcol = kb + (((lane >> 3) & 1) << 4);
        uint32_t br[16];
#pragma unroll
        for (int gg = 0; gg < 4; gg++)
            ldmx4(br + gg * 4, w_base + swz((nbase + gg * 16 + brow) * 128 + bcol));
#pragma unroll
        for (int mt = 0; mt < 2; mt++)
#pragma unroll
            for (int t = 0; t < 8; t++)
                mma16816(acc[mt * 8 + t], ar + mt * 4, br + (t >> 1) * 4 + (t & 1) * 2);
    }
}

__device__ __forceinline__ void store_H(char* hbase, float (&acc)[16][4],
                                        const float* __restrict__ b1s, int lane, int wid) {
    const int wrow0 = (wid >> 1) * 32;
    const int nbase = (wid & 1) * 64;
    int g = lane >> 2, tig = lane & 3;
#pragma unroll
    for (int mt = 0; mt < 2; mt++)
#pragma unroll
        for (int nt = 0; nt < 8; nt++) {
            int n = nbase + nt * 8 + 2 * tig;
            int half = n >> 6, kk = n & 63;
            float bz0 = b1s[n], bz1 = b1s[n + 1];
            const float* a = acc[mt * 8 + nt];
            int r0 = wrow0 + mt * 16 + g, r1 = r0 + 8;
            __half2 p0 = __floats2half2_rn(fmaxf(a[0] + bz0, 0.0f), fmaxf(a[1] + bz1, 0.0f));
            __half2 p1 = __floats2half2_rn(fmaxf(a[2] + bz0, 0.0f), fmaxf(a[3] + bz1, 0.0f));
            char* dh = hbase + half * 16384;
            *(uint32_t*)(dh + swz(r0 * 128 + kk * 2)) = *(uint32_t*)&p0;
            *(uint32_t*)(dh + swz(r1 * 128 + kk * 2)) = *(uint32_t*)&p1;
        }
}

__device__ __forceinline__ void epi_direct(float (&acc)[16][4], const float* __restrict__ bs,
                                           size_t rowbase, const float* __restrict__ inv,
                                           __half* __restrict__ outh,
                                           float* __restrict__ outf, int lane, int wid) {
    const int wrow0 = (wid >> 1) * 32;
    const int nbase = (wid & 1) * 64;
    int g = lane >> 2, tig = lane & 3;
#pragma unroll
    for (int mt = 0; mt < 2; mt++) {
        int r0 = wrow0 + mt * 16 + g, r1 = r0 + 8;
        float s0 = inv ? inv[rowbase + r0] : 1.0f;
        float s1 = inv ? inv[rowbase + r1] : 1.0f;
#pragma unroll
        for (int nt = 0; nt < 8; nt++) {
            int n = nbase + nt * 8 + 2 * tig;
            const float* a = acc[mt * 8 + nt];
            float v0 = (a[0] + bs[n]) * s0, v1 = (a[1] + bs[n + 1]) * s0;
            float v2 = (a[2] + bs[n]) * s1, v3 = (a[3] + bs[n + 1]) * s1;
            if (outh) {
                __half2 p0 = __floats2half2_rn(v0, v1);
                __half2 p1 = __floats2half2_rn(v2, v3);
                *(__half2*)(outh + (rowbase + r0) * 128 + n) = p0;
                *(__half2*)(outh + (rowbase + r1) * 128 + n) = p1;
            }
            if (outf) {
                *(float2*)(outf + (rowbase + r0) * 128 + n) = make_float2(v0, v1);
                *(float2*)(outf + (rowbase + r1) * 128 + n) = make_float2(v2, v3);
            }
        }
    }
}

#define ZERO_ACC(acc) do {                       \
    _Pragma("unroll")                            \
    for (int t_ = 0; t_ < 16; t_++)              \
        _Pragma("unroll")                        \
        for (int j_ = 0; j_ < 4; j_++) (acc)[t_][j_] = 0.0f; } while (0)

// ================= parametrized MLP kernel (R11 core) =================
// L task: nstep=8, wA=0, wB=8, rx2=1, outputs msg(inv) then l2lout.
// C task: nstep=4, wA=4, rx2=0, output msg(inv).
__global__ __launch_bounds__(256, 1) void k_mlp(
    const __half* __restrict__ X,
    const float* __restrict__ b1, const float* __restrict__ b2,
    const float* __restrict__ b3, const float* __restrict__ b4,
    const float* __restrict__ inv, __half* __restrict__ msg,
    __half* __restrict__ l2lout, int nstep, int wA, int wB, int rx2) {
    extern __shared__ __align__(1024) char sm[];
    uint32_t smem_base = smem_u32(sm);
    float* bs = (float*)sm;
    int tid = threadIdx.x, wid = tid >> 5, lane = tid & 31;
    size_t rowbase = (size_t)blockIdx.x * 128;

    for (int i = tid; i < nstep * 64; i += 256) {
        const float* src = (i < 128) ? b1 : (i < 256) ? b2 : (i < 384) ? b3 : b4;
        bs[i] = src[i & 127];
    }

    uint32_t AB = smem_base + M_A, HB = smem_base + M_H, WB = smem_base + M_W;
    issue_A_full(AB, X, rowbase, tid);
    issue_W(WB, wA, tid);
    CP_COMMIT();
    issue_W(WB + 16384, wA + 1, tid);
    CP_COMMIT();
    issue_W(WB + 32768, wA + 2, tid);
    CP_COMMIT();

    float acc[16][4];
    ZERO_ACC(acc);

#pragma unroll 1
    for (int j = 0; j < nstep; j++) {
        if (j == 0) CP_WAIT(2);
        else if (j == nstep - 1) CP_WAIT(0);
        else CP_WAIT(1);
        __syncthreads();
        if (j >= 1 && j + 2 < nstep) {
            int im = j + 2;
            int wimg = (im < 4) ? (wA + im) : (wB + im - 4);
            issue_W(WB + (im % 3) * 16384, wimg, tid);
            CP_COMMIT();
        }
        int ph = j >> 1;
        bool p2 = (ph & 1) != 0;
        uint32_t abase = (p2 ? HB : AB) + (j & 1) * 16384;
        int rxor = (ph == 2 && rx2) ? 1 : 0;
        warp_mma_k64(acc, abase, WB + (j % 3) * 16384, lane, wid, rxor);

        if (j & 1) {
            if (!p2) {
                store_H(sm + M_H, acc, bs + ((ph >> 1) * 256), lane, wid);
            } else {
                const float* bb = bs + 128 + ((ph >> 1) * 256);
                if (ph == 1) epi_direct(acc, bb, rowbase, inv, msg, nullptr, lane, wid);
                else epi_direct(acc, bb, rowbase, nullptr, l2lout, nullptr, lane, wid);
            }
            ZERO_ACC(acc);
        }
    }
}

// ================= parametrized update kernel (R11 core, occ 2) =================
__global__ __launch_bounds__(256, 2) void k_upd(
    const __half* __restrict__ S0, const __half* __restrict__ S1,
    const __half* __restrict__ S2, const float* __restrict__ bias,
    __half* __restrict__ outh, float* __restrict__ fo, int H, int whalf) {
    extern __shared__ __align__(1024) char sm[];
    uint32_t smem_base = smem_u32(sm);
    float* bs = (float*)sm;
    int tid = threadIdx.x, wid = tid >> 5, lane = tid & 31;
    size_t rowbase = (size_t)blockIdx.x * 128;

    if (tid < 128) bs[tid] = bias[tid];

    const __half* S[3] = {S0, S1, S2};

#pragma unroll
    for (int s = 0; s < 3; s++) {
        issue_half(smem_base + U_SL + s * 32768, S[s >> 1], rowbase, s & 1,
                   whalf + s, tid);
        CP_COMMIT();
    }

    float acc[16][4];
    ZERO_ACC(acc);

#pragma unroll 1
    for (int h = 0; h < H; h++) {
        if (h == 0) CP_WAIT(2);
        else if (h == H - 1) CP_WAIT(0);
        else CP_WAIT(1);
        __syncthreads();
        if (h >= 1 && h + 2 < H) {
            int s = h + 2;
            issue_half(smem_base + U_SL + (s % 3) * 32768, S[s >> 1], rowbase,
                       s & 1, whalf + s, tid);
            CP_COMMIT();
        }
        uint32_t slot = smem_base + U_SL + (h % 3) * 32768;
        warp_mma_k64(acc, slot, slot + 16384, lane, wid, 0);
    }

    epi_direct(acc, bs, rowbase, nullptr, outh, fo, lane, wid);
}

// ================= CSR aggregation (parametrized) =================
__global__ void k_aggr(const __half* __restrict__ msg, const int* __restrict__ adj,
                       const int* __restrict__ off, const int* __restrict__ cnt,
                       const float* __restrict__ inv, __half* __restrict__ out) {
    int node = blockIdx.x * 8 + (threadIdx.x >> 5);
    int lane = threadIdx.x & 31;
    int o = off[node], d = cnt[node];
    float4 acc = make_float4(0.f, 0.f, 0.f, 0.f);
    float4 acc2 = make_float4(0.f, 0.f, 0.f, 0.f);
    int j = 0;
    for (; j + 2 <= d; j += 2) {
        int s0 = adj[o + j], s1 = adj[o + j + 1];
        uint2 r0 = *(const uint2*)(msg + (size_t)s0 * D + lane * 4);
        uint2 r1 = *(const uint2*)(msg + (size_t)s1 * D + lane * 4);
        float2 a0 = __half22float2(*(__half2*)&r0.x);
        float2 a1 = __half22float2(*(__half2*)&r0.y);
        float2 b0 = __half22float2(*(__half2*)&r1.x);
        float2 b1 = __half22float2(*(__half2*)&r1.y);
        acc.x += a0.x; acc.y += a0.y; acc.z += a1.x; acc.w += a1.y;
        acc2.x += b0.x; acc2.y += b0.y; acc2.z += b1.x; acc2.w += b1.y;
    }
    if (j < d) {
        int s0 = adj[o + j];
        uint2 r0 = *(const uint2*)(msg + (size_t)s0 * D + lane * 4);
        float2 a0 = __half22float2(*(__half2*)&r0.x);
        float2 a1 = __half22float2(*(__half2*)&r0.y);
        acc.x += a0.x; acc.y += a0.y; acc.z += a1.x; acc.w += a1.y;
    }
    acc.x += acc2.x; acc.y += acc2.y; acc.z += acc2.z; acc.w += acc2.w;
    float sc = inv[node];
    __half2 p0 = __floats2half2_rn(acc.x * sc, acc.y * sc);
    __half2 p1 = __floats2half2_rn(acc.z * sc, acc.w * sc);
    uint2 res;
    res.x = *(uint32_t*)&p0;
    res.y = *(uint32_t*)&p1;
    *(uint2*)(out + (size_t)node * D + lane * 4) = res;
}

// ================= host launcher (dual-stream DAG) =================
extern "C" void kernel_launch(void* const* d_in, const int* in_sizes, int n_in,
                              void* d_out, int out_size) {
    const void* l_ei = d_in[0];
    const void* c_ei = d_in[1];
    const float* l_init = (const float*)d_in[2];
    const float* c_init = (const float*)d_in[3];
    const float* w_l2c1 = (const float*)d_in[4],  *b_l2c1 = (const float*)d_in[5];
    const float* w_l2c2 = (const float*)d_in[6],  *b_l2c2 = (const float*)d_in[7];
    const float* w_c2l1 = (const float*)d_in[8],  *b_c2l1 = (const float*)d_in[9];
    const float* w_c2l2 = (const float*)d_in[10], *b_c2l2 = (const float*)d_in[11];
    const float* w_l2l1 = (const float*)d_in[12], *b_l2l1 = (const float*)d_in[13];
    const float* w_l2l2 = (const float*)d_in[14], *b_l2l2 = (const float*)d_in[15];
    const float* w_cu   = (const float*)d_in[16], *b_cu   = (const float*)d_in[17];
    const float* w_lu   = (const float*)d_in[18], *b_lu   = (const float*)d_in[19];
    (void)in_sizes; (void)n_in; (void)out_size;

    __half *lemb, *cemb, *l2l, *agl, *agc, *msg_l, *msg_c;
    float *inv_l, *inv_c;
    int *adj_l, *adj_c, *off_l, *off_c, *cnt_l, *cnt_c;
    cudaGetSymbolAddress((void**)&lemb, g_lemb);
    cudaGetSymbolAddress((void**)&cemb, g_cemb);
    cudaGetSymbolAddress((void**)&l2l, g_l2l);
    cudaGetSymbolAddress((void**)&agl, g_agl);
    cudaGetSymbolAddress((void**)&agc, g_agc);
    cudaGetSymbolAddress((void**)&msg_l, g_msg_l);
    cudaGetSymbolAddress((void**)&msg_c, g_msg_c);
    cudaGetSymbolAddress((void**)&inv_l, g_inv_l);
    cudaGetSymbolAddress((void**)&inv_c, g_inv_c);
    cudaGetSymbolAddress((void**)&adj_l, g_adj_l);
    cudaGetSymbolAddress((void**)&adj_c, g_adj_c);
    cudaGetSymbolAddress((void**)&off_l, g_off_l);
    cudaGetSymbolAddress((void**)&off_c, g_off_c);
    cudaGetSymbolAddress((void**)&cnt_l, g_cnt_l);
    cudaGetSymbolAddress((void**)&cnt_c, g_cnt_c);

    static cudaStream_t s1 = nullptr;
    static cudaEvent_t evS, evA, evB, evC, evD;
    if (!s1) {
        cudaStreamCreateWithFlags(&s1, cudaStreamNonBlocking);
        cudaEventCreateWithFlags(&evS, cudaEventDisableTiming);
        cudaEventCreateWithFlags(&evA, cudaEventDisableTiming);
        cudaEventCreateWithFlags(&evB, cudaEventDisableTiming);
        cudaEventCreateWithFlags(&evC, cudaEventDisableTiming);
        cudaEventCreateWithFlags(&evD, cudaEventDisableTiming);
        cudaFuncSetAttribute(k_mlp, cudaFuncAttributeMaxDynamicSharedMemorySize, SMEM_MLP);
        cudaFuncSetAttribute(k_upd, cudaFuncAttributeMaxDynamicSharedMemorySize, SMEM_UPD);
    }

    // ---- setup on default stream ----
    k_zero_detect<<<384, 256>>>((const unsigned*)l_ei);
    k_hist<<<E_SIZE / 256, 256>>>(l_ei, c_ei);
    k_bsum_all<<<96, 256>>>();
    k_scanw_wprep<<<118, 256>>>(w_l2c1, w_l2c2, w_c2l1, w_c2l2, w_l2l1, w_l2l2, w_cu, w_lu);
    k_fill_inv_init<<<7424, 256>>>(l_ei, c_ei, l_init, c_init);
    cudaEventRecord(evS, 0);
    cudaStreamWaitEvent(s1, evS, 0);

    // ---- message-passing: dual-stream DAG ----
    for (int it = 0; it < N_ITERS; it++) {
        // s0: mlpL -> aggrC -> updL ; s1: mlpC -> aggrL -> updC
        k_mlp<<<NL_CTA, 256, SMEM_MLP>>>(lemb, b_l2c1, b_l2c2, b_l2l1, b_l2l2,
                                         inv_l, msg_l, l2l, 8, 0, 8, 1);
        k_mlp<<<NC_CTA, 256, SMEM_MLP, s1>>>(cemb, b_c2l1, b_c2l2, b_c2l1, b_c2l2,
                                             inv_c, msg_c, nullptr, 4, 4, 0, 0);

        if (it > 0) cudaStreamWaitEvent(0, evC, 0);      // agc WAR vs updC(it-1)
        k_aggr<<<C_SIZE / 8, 256>>>(msg_l, adj_c, off_c, cnt_c, inv_c, agc);
        cudaEventRecord(evA, 0);

        if (it > 0) cudaStreamWaitEvent(s1, evD, 0);     // agl WAR vs updL(it-1)
        k_aggr<<<L_SIZE / 8, 256, 0, s1>>>(msg_c, adj_l, off_l, cnt_l, inv_l, agl);
        cudaEventRecord(evB, s1);

        cudaStreamWaitEvent(0, evB, 0);                  // updL needs agl
        float* fo = (it == N_ITERS - 1) ? (float*)d_out : nullptr;
        k_upd<<<NL_CTA, 256, SMEM_UPD>>>(lemb, agl, l2l, b_lu, lemb, fo, 6, 16);
        cudaEventRecord(evD, 0);

        cudaStreamWaitEvent(s1, evA, 0);                 // updC needs agc
        k_upd<<<NC_CTA, 256, SMEM_UPD, s1>>>(cemb, agc, cemb, b_cu, cemb, nullptr, 4, 12);
        cudaEventRecord(evC, s1);
    }
    cudaStreamWaitEvent(0, evC, 0);                      // join s1 into default
}